// round 3
// baseline (speedup 1.0000x reference)
#include <cuda_runtime.h>
#include <math.h>
#include <stdint.h>

#define S_  32
#define T_  64
#define B_  64
#define C_  5

// ---------------- scratch (device globals; no allocation) ----------------
__device__ float g_xg_intra[(size_t)2*S_*T_*B_*384]; // [dir][s][t][b][384]
__device__ float g_intra_out[(size_t)S_*T_*B_*256];  // [s][t][b][256] fwd|bwd
__device__ float g_a1[S_*T_*B_];
__device__ float g_sent[S_*B_*256];
__device__ float g_xg_inter[2*S_*B_*384];            // [dir][s][b][384]
__device__ float g_inter_out[S_*B_*256];
__device__ float g_a2[S_*B_];

__device__ __forceinline__ float sigm(float x) { return 1.f / (1.f + expf(-x)); }

// ---------------- K2: input-gate GEMM (optionally gathered A) -------------
// rows: rb*64+b (flattened [S,T,B] or [S,B]); cols: cb*128 + cg + 32m in [0,768)
// out[((dir*nrb+rb)*64+b)*384+g] = bias[col] + sum_e Arow[e]*W[col][e]
template<int KDIM>
__global__ void k_gemm_xg(const int* __restrict__ tokens,
                          const float* __restrict__ A,
                          const float* __restrict__ W,
                          const float* __restrict__ bias,
                          float* __restrict__ out,
                          int nrb) {
    extern __shared__ float sm[];
    float* As = sm;                       // 64*132
    float* Wt = sm + 64 * 132;            // 128*129 ([e][c])
    int*   toks = (int*)(Wt + 128 * 129); // 64
    const int rb = blockIdx.x, cb = blockIdx.y;
    const int tid = threadIdx.x;
    if (tokens && tid < 64) toks[tid] = tokens[rb * 64 + tid];
    __syncthreads();

    const int cg = tid & 31, bg = tid >> 5;
    float acc[8][4];
#pragma unroll
    for (int i = 0; i < 8; i++)
#pragma unroll
        for (int m = 0; m < 4; m++) acc[i][m] = 0.f;

    for (int kc = 0; kc < KDIM / 128; kc++) {
        for (int idx = tid; idx < 64 * 128; idx += 256) {
            int b = idx >> 7, e = idx & 127;
            const float* arow = tokens ? (A + (size_t)toks[b] * KDIM)
                                       : (A + (size_t)(rb * 64 + b) * KDIM);
            As[b * 132 + e] = arow[kc * 128 + e];
        }
        for (int idx = tid; idx < 128 * 128; idx += 256) {
            int c = idx >> 7, e = idx & 127;
            Wt[e * 129 + c] = W[(size_t)(cb * 128 + c) * KDIM + kc * 128 + e];
        }
        __syncthreads();
#pragma unroll 4
        for (int e = 0; e < 128; e++) {
            float a[8], w[4];
#pragma unroll
            for (int i = 0; i < 8; i++) a[i] = As[(bg * 8 + i) * 132 + e];
#pragma unroll
            for (int m = 0; m < 4; m++) w[m] = Wt[e * 129 + cg + 32 * m];
#pragma unroll
            for (int i = 0; i < 8; i++)
#pragma unroll
                for (int m = 0; m < 4; m++) acc[i][m] = fmaf(a[i], w[m], acc[i][m]);
        }
        __syncthreads();
    }
#pragma unroll
    for (int m = 0; m < 4; m++) {
        int col = cb * 128 + cg + 32 * m;
        int dir = col >= 384 ? 1 : 0;
        int g = col - dir * 384;
        float bv = bias[col];
#pragma unroll
        for (int i = 0; i < 8; i++) {
            int brow = bg * 8 + i;
            out[(((size_t)dir * nrb + rb) * 64 + brow) * 384 + g] = acc[i][m] + bv;
        }
    }
}

// ---------------- K3a: intra biGRU, all 64 steps, one launch --------------
// grid 128: dir = bx>>6, s = (bx>>1)&31, bhalf = bx&1 (32 batch rows/block)
__global__ void k_gru_intra(const float* __restrict__ xg,
                            const float* __restrict__ Whh,
                            const float* __restrict__ bhh,
                            float* __restrict__ out) {
    extern __shared__ float sm[];
    float* Ws = sm;              // 384*133
    float* hs = sm + 384 * 133;  // 32*133
    const int bx = blockIdx.x;
    const int dir = bx >> 6, s = (bx >> 1) & 31, bh = bx & 1;
    const int b0 = bh * 32;
    const int tid = threadIdx.x;
    const int jg = tid & 31, bg = tid >> 5;

    for (int idx = tid; idx < 384 * 128; idx += 256) {
        int row = idx >> 7, k = idx & 127;
        Ws[row * 133 + k] = Whh[dir * 384 * 128 + idx];
    }
    for (int idx = tid; idx < 32 * 133; idx += 256) hs[idx] = 0.f;
    __syncthreads();

    float br[4], bz[4], bn[4];
#pragma unroll
    for (int m = 0; m < 4; m++) {
        int j = jg + 32 * m;
        br[m] = bhh[dir * 384 + j];
        bz[m] = bhh[dir * 384 + 128 + j];
        bn[m] = bhh[dir * 384 + 256 + j];
    }

    for (int tt = 0; tt < 64; tt++) {
        const int t = dir ? (63 - tt) : tt;
        float ar[4][4], az[4][4], an[4][4];
#pragma unroll
        for (int i = 0; i < 4; i++)
#pragma unroll
            for (int m = 0; m < 4; m++) { ar[i][m] = 0.f; az[i][m] = 0.f; an[i][m] = 0.f; }

#pragma unroll 2
        for (int k = 0; k < 128; k++) {
            float hv[4];
#pragma unroll
            for (int i = 0; i < 4; i++) hv[i] = hs[(bg * 4 + i) * 133 + k];
#pragma unroll
            for (int m = 0; m < 4; m++) {
                int ro = (jg + 32 * m) * 133 + k;
                float wr = Ws[ro];
                float wz = Ws[ro + 128 * 133];
                float wn = Ws[ro + 256 * 133];
#pragma unroll
                for (int i = 0; i < 4; i++) {
                    ar[i][m] = fmaf(hv[i], wr, ar[i][m]);
                    az[i][m] = fmaf(hv[i], wz, az[i][m]);
                    an[i][m] = fmaf(hv[i], wn, an[i][m]);
                }
            }
        }

        const float* xgb = xg + ((((size_t)dir * 32 + s) * 64 + t) * 64 + b0) * 384;
        float* ob = out + (((size_t)s * 64 + t) * 64 + b0) * 256 + dir * 128;
        float hn[4][4];
#pragma unroll
        for (int i = 0; i < 4; i++) {
            int bl = bg * 4 + i;
            const float* xr = xgb + (size_t)bl * 384;
#pragma unroll
            for (int m = 0; m < 4; m++) {
                int j = jg + 32 * m;
                float r = sigm(xr[j] + ar[i][m] + br[m]);
                float z = sigm(xr[128 + j] + az[i][m] + bz[m]);
                float n = tanhf(xr[256 + j] + r * (an[i][m] + bn[m]));
                float ho = hs[bl * 133 + j];
                float hv2 = (1.f - z) * n + z * ho;
                hn[i][m] = hv2;
                ob[(size_t)bl * 256 + j] = hv2;
            }
        }
        __syncthreads();
#pragma unroll
        for (int i = 0; i < 4; i++)
#pragma unroll
            for (int m = 0; m < 4; m++) hs[(bg * 4 + i) * 133 + jg + 32 * m] = hn[i][m];
        __syncthreads();
    }
}

// ---------------- K3b: inter biGRU, all 32 steps, one launch --------------
// grid 64: dir = bx>>5, batch-pair = bx&31
__global__ void k_gru_inter(const float* __restrict__ xg,
                            const float* __restrict__ Whh,
                            const float* __restrict__ bhh,
                            float* __restrict__ out) {
    extern __shared__ float sm[];
    float* Ws = sm;              // 384*133
    float* hs = sm + 384 * 133;  // 2*132
    const int bx = blockIdx.x;
    const int dir = bx >> 5;
    const int b0 = (bx & 31) * 2;
    const int tid = threadIdx.x;
    const int bl = tid >> 7;
    const int j = tid & 127;

    for (int idx = tid; idx < 384 * 128; idx += 256) {
        int row = idx >> 7, k = idx & 127;
        Ws[row * 133 + k] = Whh[dir * 384 * 128 + idx];
    }
    for (int idx = tid; idx < 2 * 132; idx += 256) hs[idx] = 0.f;
    __syncthreads();

    const float br = bhh[dir * 384 + j];
    const float bz = bhh[dir * 384 + 128 + j];
    const float bn = bhh[dir * 384 + 256 + j];

    for (int tt = 0; tt < 32; tt++) {
        const int sstep = dir ? (31 - tt) : tt;
        float ar = 0.f, az = 0.f, an = 0.f;
#pragma unroll 4
        for (int k = 0; k < 128; k++) {
            float hv = hs[bl * 132 + k];
            int ro = j * 133 + k;
            ar = fmaf(hv, Ws[ro], ar);
            az = fmaf(hv, Ws[ro + 128 * 133], az);
            an = fmaf(hv, Ws[ro + 256 * 133], an);
        }
        const int b = b0 + bl;
        const float* xr = xg + (((size_t)dir * 32 + sstep) * 64 + b) * 384;
        float r = sigm(xr[j] + ar + br);
        float z = sigm(xr[128 + j] + az + bz);
        float n = tanhf(xr[256 + j] + r * (an + bn));
        float ho = hs[bl * 132 + j];
        float hv2 = (1.f - z) * n + z * ho;
        out[((size_t)sstep * 64 + b) * 256 + dir * 128 + j] = hv2;
        __syncthreads();
        hs[bl * 132 + j] = hv2;
        __syncthreads();
    }
}

// ---------------- K4a: attention logits: proj . tanh(X W + b) -------------
__global__ void k_attn_logits(const float* __restrict__ X,
                              const float* __restrict__ W,   // [256][256] h-major
                              const float* __restrict__ bb,
                              const float* __restrict__ proj,
                              float* __restrict__ logits) {
    extern __shared__ float sm[];
    float* Xs = sm;            // 64*68
    float* Wt = sm + 64 * 68;  // 64*260
    const int rb = blockIdx.x;
    const int tid = threadIdx.x;
    const int cg = tid & 31, bg = tid >> 5;
    float acc[8][8];
#pragma unroll
    for (int i = 0; i < 8; i++)
#pragma unroll
        for (int m = 0; m < 8; m++) acc[i][m] = 0.f;

    for (int hc = 0; hc < 4; hc++) {
        for (int idx = tid; idx < 64 * 64; idx += 256) {
            int r = idx >> 6, hl = idx & 63;
            Xs[r * 68 + hl] = X[((size_t)rb * 64 + r) * 256 + hc * 64 + hl];
        }
        for (int idx = tid; idx < 64 * 256; idx += 256) {
            int hl = idx >> 8, k = idx & 255;
            Wt[hl * 260 + k] = W[(size_t)(hc * 64 + hl) * 256 + k];
        }
        __syncthreads();
#pragma unroll 2
        for (int hl = 0; hl < 64; hl++) {
            float a[8], w[8];
#pragma unroll
            for (int i = 0; i < 8; i++) a[i] = Xs[(bg * 8 + i) * 68 + hl];
#pragma unroll
            for (int m = 0; m < 8; m++) w[m] = Wt[hl * 260 + cg + 32 * m];
#pragma unroll
            for (int i = 0; i < 8; i++)
#pragma unroll
                for (int m = 0; m < 8; m++) acc[i][m] = fmaf(a[i], w[m], acc[i][m]);
        }
        __syncthreads();
    }

    float part[8];
#pragma unroll
    for (int i = 0; i < 8; i++) part[i] = 0.f;
#pragma unroll
    for (int m = 0; m < 8; m++) {
        int col = cg + 32 * m;
        float bv = bb[col], pv = proj[col];
#pragma unroll
        for (int i = 0; i < 8; i++) part[i] += pv * tanhf(acc[i][m] + bv);
    }
#pragma unroll
    for (int i = 0; i < 8; i++) {
        float v = part[i];
#pragma unroll
        for (int off = 16; off > 0; off >>= 1) v += __shfl_xor_sync(0xffffffffu, v, off);
        if (cg == 0) logits[(size_t)rb * 64 + bg * 8 + i] = v;
    }
}

// ---------------- K4b: softmax over t, in place ---------------------------
__global__ void k_softmax_t(float* __restrict__ a) {
    int gid = blockIdx.x * blockDim.x + threadIdx.x;
    if (gid >= S_ * B_) return;
    int s = gid >> 6, b = gid & 63;
    size_t base = (size_t)s * 4096 + b;
    float mx = -1e30f;
    for (int t = 0; t < 64; t++) mx = fmaxf(mx, a[base + t * 64]);
    float sum = 0.f;
    for (int t = 0; t < 64; t++) sum += expf(a[base + t * 64] - mx);
    float inv = 1.f / sum;
    for (int t = 0; t < 64; t++) a[base + t * 64] = expf(a[base + t * 64] - mx) * inv;
}

// ---------------- K4c: sentence vectors: sum_t a1 * X ---------------------
__global__ void k_sent(const float* __restrict__ a1,
                       const float* __restrict__ X,
                       float* __restrict__ sent) {
    const int s = blockIdx.x, bg = blockIdx.y;
    const int h = threadIdx.x;
    float acc[8];
#pragma unroll
    for (int ib = 0; ib < 8; ib++) acc[ib] = 0.f;
    for (int t = 0; t < 64; t++) {
#pragma unroll
        for (int ib = 0; ib < 8; ib++) {
            int b = bg * 8 + ib;
            size_t row = (size_t)s * 4096 + (size_t)t * 64 + b;
            acc[ib] = fmaf(a1[row], X[row * 256 + h], acc[ib]);
        }
    }
#pragma unroll
    for (int ib = 0; ib < 8; ib++)
        sent[((size_t)s * 64 + bg * 8 + ib) * 256 + h] = acc[ib];
}

// ---------------- K7: doc vector + final linear ---------------------------
__global__ void k_doc_final(const float* __restrict__ a2,
                            const float* __restrict__ Xo,
                            const float* __restrict__ Wf,
                            const float* __restrict__ bf,
                            float* __restrict__ outp) {
    __shared__ float red[256];
    const int b = blockIdx.x, h = threadIdx.x;
    float dh = 0.f;
    for (int s2 = 0; s2 < 32; s2++) {
        size_t row = (size_t)s2 * 64 + b;
        dh = fmaf(a2[row], Xo[row * 256 + h], dh);
    }
    for (int c = 0; c < C_; c++) {
        red[h] = dh * Wf[c * 256 + h];
        __syncthreads();
        for (int off = 128; off > 0; off >>= 1) {
            if (h < off) red[h] += red[h + off];
            __syncthreads();
        }
        if (h == 0) outp[b * C_ + c] = red[0] + bf[c];
        __syncthreads();
    }
}

// ---------------- launch ---------------------------------------------------
extern "C" void kernel_launch(void* const* d_in, const int* in_sizes, int n_in,
                              void* d_out, int out_size) {
    const int*   tokens = (const int*)d_in[0];
    const float* embed  = (const float*)d_in[1];
    const float* Wih_a  = (const float*)d_in[2];
    const float* Whh_a  = (const float*)d_in[3];
    const float* bih_a  = (const float*)d_in[4];
    const float* bhh_a  = (const float*)d_in[5];
    const float* WW_a   = (const float*)d_in[6];
    const float* b_a    = (const float*)d_in[7];
    const float* proj_a = (const float*)d_in[8];
    const float* Wih_e  = (const float*)d_in[9];
    const float* Whh_e  = (const float*)d_in[10];
    const float* bih_e  = (const float*)d_in[11];
    const float* bhh_e  = (const float*)d_in[12];
    const float* WW_e   = (const float*)d_in[13];
    const float* b_e    = (const float*)d_in[14];
    const float* proj_e = (const float*)d_in[15];
    const float* Wf     = (const float*)d_in[16];
    const float* bf     = (const float*)d_in[17];
    float* outp = (float*)d_out;

    void *xga_p, *io_p, *a1_p, *sent_p, *xge_p, *ioe_p, *a2_p;
    cudaGetSymbolAddress(&xga_p, g_xg_intra);
    cudaGetSymbolAddress(&io_p, g_intra_out);
    cudaGetSymbolAddress(&a1_p, g_a1);
    cudaGetSymbolAddress(&sent_p, g_sent);
    cudaGetSymbolAddress(&xge_p, g_xg_inter);
    cudaGetSymbolAddress(&ioe_p, g_inter_out);
    cudaGetSymbolAddress(&a2_p, g_a2);

    const int sm_gemm  = (64 * 132 + 128 * 129) * 4 + 64 * 4;
    const int sm_intra = (384 * 133 + 32 * 133) * 4;
    const int sm_inter = (384 * 133 + 2 * 132) * 4;
    const int sm_attn  = (64 * 68 + 64 * 260) * 4;
    cudaFuncSetAttribute(k_gemm_xg<128>, cudaFuncAttributeMaxDynamicSharedMemorySize, sm_gemm);
    cudaFuncSetAttribute(k_gemm_xg<256>, cudaFuncAttributeMaxDynamicSharedMemorySize, sm_gemm);
    cudaFuncSetAttribute(k_gru_intra, cudaFuncAttributeMaxDynamicSharedMemorySize, sm_intra);
    cudaFuncSetAttribute(k_gru_inter, cudaFuncAttributeMaxDynamicSharedMemorySize, sm_inter);
    cudaFuncSetAttribute(k_attn_logits, cudaFuncAttributeMaxDynamicSharedMemorySize, sm_attn);

    // 1) intra input gates (gathered embedding GEMM): rows = S*T*B
    k_gemm_xg<128><<<dim3(2048, 6), 256, sm_gemm>>>(tokens, embed, Wih_a, bih_a,
                                                    (float*)xga_p, 2048);
    // 2) intra biGRU, 64 steps in one launch
    k_gru_intra<<<128, 256, sm_intra>>>((float*)xga_p, Whh_a, bhh_a, (float*)io_p);
    // 3) word attention logits
    k_attn_logits<<<2048, 256, sm_attn>>>((float*)io_p, WW_a, b_a, proj_a, (float*)a1_p);
    // 4) softmax over tokens
    k_softmax_t<<<8, 256>>>((float*)a1_p);
    // 5) sentence vectors
    k_sent<<<dim3(32, 8), 256>>>((float*)a1_p, (float*)io_p, (float*)sent_p);
    // 6) inter input gates
    k_gemm_xg<256><<<dim3(32, 6), 256, sm_gemm>>>(nullptr, (float*)sent_p, Wih_e, bih_e,
                                                  (float*)xge_p, 32);
    // 7) inter biGRU, 32 steps in one launch
    k_gru_inter<<<64, 256, sm_inter>>>((float*)xge_p, Whh_e, bhh_e, (float*)ioe_p);
    // 8) sentence attention logits (NO softmax)
    k_attn_logits<<<32, 256, sm_attn>>>((float*)ioe_p, WW_e, b_e, proj_e, (float*)a2_p);
    // 9) doc vector + final linear
    k_doc_final<<<64, 256>>>((float*)a2_p, (float*)ioe_p, Wf, bf, outp);
}

// round 5
// speedup vs baseline: 1.3442x; 1.3442x over previous
#include <cuda_runtime.h>
#include <math.h>
#include <stdint.h>

#define S_  32
#define T_  64
#define B_  64
#define C_  5

// ---------------- scratch (device globals; no allocation) ----------------
__device__ float g_xg_intra[(size_t)2*S_*T_*B_*384]; // [dir][row(s,t,b)][384]
__device__ float g_intra_out[(size_t)S_*T_*B_*256];  // [s][t][b][256] fwd|bwd
__device__ float g_a1[S_*T_*B_];
__device__ float g_sent[S_*B_*256];
__device__ float g_xg_inter[2*S_*B_*384];            // [dir][row(s,b)][384]
__device__ float g_inter_out[S_*B_*256];
__device__ float g_a2[S_*B_];

__device__ __forceinline__ float sigm(float x) { return 1.f / (1.f + expf(-x)); }

__device__ __forceinline__ uint32_t f2tf(float f) {
    uint32_t o;
    asm("cvt.rna.tf32.f32 %0, %1;" : "=r"(o) : "f"(f));
    return o;
}

__device__ __forceinline__ void mma_tf32(float c[4],
                                         uint32_t a0, uint32_t a1, uint32_t a2, uint32_t a3,
                                         uint32_t b0, uint32_t b1) {
    asm volatile(
        "mma.sync.aligned.m16n8k8.row.col.f32.tf32.tf32.f32 "
        "{%0,%1,%2,%3}, {%4,%5,%6,%7}, {%8,%9}, {%0,%1,%2,%3};"
        : "+f"(c[0]), "+f"(c[1]), "+f"(c[2]), "+f"(c[3])
        : "r"(a0), "r"(a1), "r"(a2), "r"(a3), "r"(b0), "r"(b1));
}

// ================= K2 (tensor): input-gate GEMM, optionally gathered A ====
// C[row, col] = bias[col] + sum_k A[row,k] * W[col,k]; cols 0..767, dir=col/384
// out[((dir*nrows + row)*384 + g] ; block tile 128x128, A full-K resident.
template<int KDIM>
__global__ __launch_bounds__(256) void k_gemm_t(const int* __restrict__ tokens,
                                                const float* __restrict__ A,
                                                const float* __restrict__ W,
                                                const float* __restrict__ bias,
                                                float* __restrict__ out,
                                                int nrows) {
    extern __shared__ uint32_t usm[];
    const int AST = KDIM + 4;
    uint32_t* As = usm;                  // 128 x AST
    uint32_t* Bs = usm + 128 * AST;      // 128 x 68
    __shared__ int toks[128];
    const int rb = blockIdx.x, cb = blockIdx.y;
    const int tid = threadIdx.x;
    const int lane = tid & 31, wid = tid >> 5;
    const int wm = wid >> 2, wn = wid & 3;   // warps: 2 (M) x 4 (N)
    const int grp = lane >> 2, t4 = lane & 3;

    if (tokens) {
        if (tid < 128) toks[tid] = tokens[rb * 128 + tid];
        __syncthreads();
    }
    // Load A tile (128 rows x KDIM), convert to tf32, vectorized
    for (int q = tid; q < 128 * (KDIM / 4); q += 256) {
        int r = q / (KDIM / 4), w4 = q % (KDIM / 4);
        const float* src = tokens ? (A + (size_t)toks[r] * KDIM + w4 * 4)
                                  : (A + (size_t)(rb * 128 + r) * KDIM + w4 * 4);
        float4 v = *(const float4*)src;
        uint4 u = make_uint4(f2tf(v.x), f2tf(v.y), f2tf(v.z), f2tf(v.w));
        *(uint4*)(As + r * AST + w4 * 4) = u;
    }

    float acc[4][4][4];
#pragma unroll
    for (int i = 0; i < 4; i++)
#pragma unroll
        for (int j = 0; j < 4; j++)
#pragma unroll
            for (int r = 0; r < 4; r++) acc[i][j][r] = 0.f;

    for (int kc = 0; kc < KDIM / 64; kc++) {
        __syncthreads();
        // B chunk: Bs[n][k] = W[cb*128+n][kc*64+k], n=0..127, k=0..63
        for (int q = tid; q < 128 * 16; q += 256) {
            int n = q >> 4, w4 = q & 15;
            float4 v = *(const float4*)(W + (size_t)(cb * 128 + n) * KDIM + kc * 64 + w4 * 4);
            uint4 u = make_uint4(f2tf(v.x), f2tf(v.y), f2tf(v.z), f2tf(v.w));
            *(uint4*)(Bs + n * 68 + w4 * 4) = u;
        }
        __syncthreads();
#pragma unroll
        for (int ks = 0; ks < 8; ks++) {
            const int k0 = kc * 64 + ks * 8;
            const int kb = ks * 8;
            uint32_t a[4][4], b[4][2];
#pragma unroll
            for (int i = 0; i < 4; i++) {
                int row = wm * 64 + i * 16 + grp;
                a[i][0] = As[row * AST + k0 + t4];
                a[i][1] = As[(row + 8) * AST + k0 + t4];
                a[i][2] = As[row * AST + k0 + t4 + 4];
                a[i][3] = As[(row + 8) * AST + k0 + t4 + 4];
            }
#pragma unroll
            for (int j = 0; j < 4; j++) {
                int n = wn * 32 + j * 8 + grp;
                b[j][0] = Bs[n * 68 + kb + t4];
                b[j][1] = Bs[n * 68 + kb + t4 + 4];
            }
#pragma unroll
            for (int i = 0; i < 4; i++)
#pragma unroll
                for (int j = 0; j < 4; j++)
                    mma_tf32(acc[i][j], a[i][0], a[i][1], a[i][2], a[i][3], b[j][0], b[j][1]);
        }
    }

    // epilogue: col -> (dir, g)
    const int dir = (cb >= 3) ? 1 : 0;
#pragma unroll
    for (int i = 0; i < 4; i++) {
        int row = rb * 128 + wm * 64 + i * 16 + grp;
#pragma unroll
        for (int j = 0; j < 4; j++) {
            int col = cb * 128 + wn * 32 + j * 8 + 2 * t4;
            int g = col - dir * 384;
            float b0v = bias[col], b1v = bias[col + 1];
            float2 v0 = make_float2(acc[i][j][0] + b0v, acc[i][j][1] + b1v);
            float2 v1 = make_float2(acc[i][j][2] + b0v, acc[i][j][3] + b1v);
            *(float2*)&out[((size_t)dir * nrows + row) * 384 + g] = v0;
            *(float2*)&out[((size_t)dir * nrows + row + 8) * 384 + g] = v1;
        }
    }
}

// ========= attention (tensor): logits[row] = proj . tanh(X W + b) =========
// X: [nrows,256]; W: [256(h)][256(k)]; block: 128 rows, full N=256, K=256
__global__ __launch_bounds__(256) void k_attn_t(const float* __restrict__ X,
                                                const float* __restrict__ W,
                                                const float* __restrict__ bb,
                                                const float* __restrict__ proj,
                                                float* __restrict__ logits) {
    extern __shared__ uint32_t usm[];
    uint32_t* As = usm;                 // 128 x 260
    uint32_t* Bs = usm + 128 * 260;     // 256 x 68
    __shared__ float part_sm[128];
    const int rb = blockIdx.x;
    const int tid = threadIdx.x;
    const int lane = tid & 31, wid = tid >> 5;
    const int wm = wid >> 2, wn = wid & 3;   // warps: 2 (M) x 4 (N) ; warp tile 64x64
    const int grp = lane >> 2, t4 = lane & 3;

    for (int q = tid; q < 128 * 64; q += 256) {
        int r = q >> 6, w4 = q & 63;
        float4 v = *(const float4*)(X + (size_t)(rb * 128 + r) * 256 + w4 * 4);
        uint4 u = make_uint4(f2tf(v.x), f2tf(v.y), f2tf(v.z), f2tf(v.w));
        *(uint4*)(As + r * 260 + w4 * 4) = u;
    }
    if (tid < 128) part_sm[tid] = 0.f;

    float acc[4][8][4];
#pragma unroll
    for (int i = 0; i < 4; i++)
#pragma unroll
        for (int j = 0; j < 8; j++)
#pragma unroll
            for (int r = 0; r < 4; r++) acc[i][j][r] = 0.f;

    for (int kc = 0; kc < 4; kc++) {
        __syncthreads();
        // Bs[n][h] = W[kc*64+h][n] (transpose load)
        for (int q = tid; q < 256 * 64; q += 256) {
            int n = q & 255, h = q >> 8;
            Bs[n * 68 + h] = f2tf(W[(size_t)(kc * 64 + h) * 256 + n]);
        }
        __syncthreads();
#pragma unroll
        for (int ks = 0; ks < 8; ks++) {
            const int k0 = kc * 64 + ks * 8;
            const int kb = ks * 8;
            uint32_t a[4][4], b[8][2];
#pragma unroll
            for (int i = 0; i < 4; i++) {
                int row = wm * 64 + i * 16 + grp;
                a[i][0] = As[row * 260 + k0 + t4];
                a[i][1] = As[(row + 8) * 260 + k0 + t4];
                a[i][2] = As[row * 260 + k0 + t4 + 4];
                a[i][3] = As[(row + 8) * 260 + k0 + t4 + 4];
            }
#pragma unroll
            for (int j = 0; j < 8; j++) {
                int n = wn * 64 + j * 8 + grp;
                b[j][0] = Bs[n * 68 + kb + t4];
                b[j][1] = Bs[n * 68 + kb + t4 + 4];
            }
#pragma unroll
            for (int i = 0; i < 4; i++)
#pragma unroll
                for (int j = 0; j < 8; j++)
                    mma_tf32(acc[i][j], a[i][0], a[i][1], a[i][2], a[i][3], b[j][0], b[j][1]);
        }
    }
    __syncthreads();

    // fused epilogue: sum_col proj[col]*tanh(c+b[col]) per row
    float rsum[4][2];
#pragma unroll
    for (int i = 0; i < 4; i++) { rsum[i][0] = 0.f; rsum[i][1] = 0.f; }
#pragma unroll
    for (int j = 0; j < 8; j++) {
        int col = wn * 64 + j * 8 + 2 * t4;
        float pv0 = proj[col], pv1 = proj[col + 1];
        float bv0 = bb[col], bv1 = bb[col + 1];
#pragma unroll
        for (int i = 0; i < 4; i++) {
            rsum[i][0] += pv0 * tanhf(acc[i][j][0] + bv0) + pv1 * tanhf(acc[i][j][1] + bv1);
            rsum[i][1] += pv0 * tanhf(acc[i][j][2] + bv0) + pv1 * tanhf(acc[i][j][3] + bv1);
        }
    }
#pragma unroll
    for (int i = 0; i < 4; i++) {
#pragma unroll
        for (int sr = 0; sr < 2; sr++) {
            float v = rsum[i][sr];
            v += __shfl_xor_sync(0xffffffffu, v, 1);
            v += __shfl_xor_sync(0xffffffffu, v, 2);
            if (t4 == 0) atomicAdd(&part_sm[wm * 64 + i * 16 + sr * 8 + grp], v);
        }
    }
    __syncthreads();
    if (tid < 128) logits[(size_t)rb * 128 + tid] = part_sm[tid];
}

// ---------------- K3a: intra biGRU, all 64 steps, one launch --------------
__global__ void k_gru_intra(const float* __restrict__ xg,
                            const float* __restrict__ Whh,
                            const float* __restrict__ bhh,
                            float* __restrict__ out) {
    extern __shared__ float sm[];
    float* Ws = sm;              // 384*133
    float* hs = sm + 384 * 133;  // 32*133
    const int bx = blockIdx.x;
    const int dir = bx >> 6, s = (bx >> 1) & 31, bh = bx & 1;
    const int b0 = bh * 32;
    const int tid = threadIdx.x;
    const int jg = tid & 31, bg = tid >> 5;

    for (int idx = tid; idx < 384 * 128; idx += 256) {
        int row = idx >> 7, k = idx & 127;
        Ws[row * 133 + k] = Whh[dir * 384 * 128 + idx];
    }
    for (int idx = tid; idx < 32 * 133; idx += 256) hs[idx] = 0.f;
    __syncthreads();

    float br[4], bz[4], bn[4];
#pragma unroll
    for (int m = 0; m < 4; m++) {
        int j = jg + 32 * m;
        br[m] = bhh[dir * 384 + j];
        bz[m] = bhh[dir * 384 + 128 + j];
        bn[m] = bhh[dir * 384 + 256 + j];
    }

    for (int tt = 0; tt < 64; tt++) {
        const int t = dir ? (63 - tt) : tt;
        float ar[4][4], az[4][4], an[4][4];
#pragma unroll
        for (int i = 0; i < 4; i++)
#pragma unroll
            for (int m = 0; m < 4; m++) { ar[i][m] = 0.f; az[i][m] = 0.f; an[i][m] = 0.f; }

#pragma unroll 2
        for (int k = 0; k < 128; k++) {
            float hv[4];
#pragma unroll
            for (int i = 0; i < 4; i++) hv[i] = hs[(bg * 4 + i) * 133 + k];
#pragma unroll
            for (int m = 0; m < 4; m++) {
                int ro = (jg + 32 * m) * 133 + k;
                float wr = Ws[ro];
                float wz = Ws[ro + 128 * 133];
                float wn = Ws[ro + 256 * 133];
#pragma unroll
                for (int i = 0; i < 4; i++) {
                    ar[i][m] = fmaf(hv[i], wr, ar[i][m]);
                    az[i][m] = fmaf(hv[i], wz, az[i][m]);
                    an[i][m] = fmaf(hv[i], wn, an[i][m]);
                }
            }
        }

        const float* xgb = xg + ((((size_t)dir * 32 + s) * 64 + t) * 64 + b0) * 384;
        float* ob = out + (((size_t)s * 64 + t) * 64 + b0) * 256 + dir * 128;
        float hn[4][4];
#pragma unroll
        for (int i = 0; i < 4; i++) {
            int bl = bg * 4 + i;
            const float* xr = xgb + (size_t)bl * 384;
#pragma unroll
            for (int m = 0; m < 4; m++) {
                int j = jg + 32 * m;
                float r = sigm(xr[j] + ar[i][m] + br[m]);
                float z = sigm(xr[128 + j] + az[i][m] + bz[m]);
                float n = tanhf(xr[256 + j] + r * (an[i][m] + bn[m]));
                float ho = hs[bl * 133 + j];
                float hv2 = (1.f - z) * n + z * ho;
                hn[i][m] = hv2;
                ob[(size_t)bl * 256 + j] = hv2;
            }
        }
        __syncthreads();
#pragma unroll
        for (int i = 0; i < 4; i++)
#pragma unroll
            for (int m = 0; m < 4; m++) hs[(bg * 4 + i) * 133 + jg + 32 * m] = hn[i][m];
        __syncthreads();
    }
}

// ---------------- K3b: inter biGRU, all 32 steps, one launch --------------
__global__ void k_gru_inter(const float* __restrict__ xg,
                            const float* __restrict__ Whh,
                            const float* __restrict__ bhh,
                            float* __restrict__ out) {
    extern __shared__ float sm[];
    float* Ws = sm;              // 384*133
    float* hs = sm + 384 * 133;  // 2*132
    const int bx = blockIdx.x;
    const int dir = bx >> 5;
    const int b0 = (bx & 31) * 2;
    const int tid = threadIdx.x;
    const int bl = tid >> 7;
    const int j = tid & 127;

    for (int idx = tid; idx < 384 * 128; idx += 256) {
        int row = idx >> 7, k = idx & 127;
        Ws[row * 133 + k] = Whh[dir * 384 * 128 + idx];
    }
    for (int idx = tid; idx < 2 * 132; idx += 256) hs[idx] = 0.f;
    __syncthreads();

    const float br = bhh[dir * 384 + j];
    const float bz = bhh[dir * 384 + 128 + j];
    const float bn = bhh[dir * 384 + 256 + j];

    for (int tt = 0; tt < 32; tt++) {
        const int sstep = dir ? (31 - tt) : tt;
        float ar = 0.f, az = 0.f, an = 0.f;
#pragma unroll 4
        for (int k = 0; k < 128; k++) {
            float hv = hs[bl * 132 + k];
            int ro = j * 133 + k;
            ar = fmaf(hv, Ws[ro], ar);
            az = fmaf(hv, Ws[ro + 128 * 133], az);
            an = fmaf(hv, Ws[ro + 256 * 133], an);
        }
        const int b = b0 + bl;
        const float* xr = xg + (((size_t)dir * 32 + sstep) * 64 + b) * 384;
        float r = sigm(xr[j] + ar + br);
        float z = sigm(xr[128 + j] + az + bz);
        float n = tanhf(xr[256 + j] + r * (an + bn));
        float ho = hs[bl * 132 + j];
        float hv2 = (1.f - z) * n + z * ho;
        out[((size_t)sstep * 64 + b) * 256 + dir * 128 + j] = hv2;
        __syncthreads();
        hs[bl * 132 + j] = hv2;
        __syncthreads();
    }
}

// ---------------- softmax over t, in place --------------------------------
__global__ void k_softmax_t(float* __restrict__ a) {
    int gid = blockIdx.x * blockDim.x + threadIdx.x;
    if (gid >= S_ * B_) return;
    int s = gid >> 6, b = gid & 63;
    size_t base = (size_t)s * 4096 + b;
    float mx = -1e30f;
    for (int t = 0; t < 64; t++) mx = fmaxf(mx, a[base + t * 64]);
    float sum = 0.f;
    for (int t = 0; t < 64; t++) sum += expf(a[base + t * 64] - mx);
    float inv = 1.f / sum;
    for (int t = 0; t < 64; t++) a[base + t * 64] = expf(a[base + t * 64] - mx) * inv;
}

// ---------------- sentence vectors: sum_t a1 * X ---------------------------
__global__ void k_sent(const float* __restrict__ a1,
                       const float* __restrict__ X,
                       float* __restrict__ sent) {
    const int s = blockIdx.x, bg = blockIdx.y;
    const int h = threadIdx.x;
    float acc[8];
#pragma unroll
    for (int ib = 0; ib < 8; ib++) acc[ib] = 0.f;
    for (int t = 0; t < 64; t++) {
#pragma unroll
        for (int ib = 0; ib < 8; ib++) {
            int b = bg * 8 + ib;
            size_t row = (size_t)s * 4096 + (size_t)t * 64 + b;
            acc[ib] = fmaf(a1[row], X[row * 256 + h], acc[ib]);
        }
    }
#pragma unroll
    for (int ib = 0; ib < 8; ib++)
        sent[((size_t)s * 64 + bg * 8 + ib) * 256 + h] = acc[ib];
}

// ---------------- doc vector + final linear --------------------------------
__global__ void k_doc_final(const float* __restrict__ a2,
                            const float* __restrict__ Xo,
                            const float* __restrict__ Wf,
                            const float* __restrict__ bf,
                            float* __restrict__ outp) {
    __shared__ float red[256];
    const int b = blockIdx.x, h = threadIdx.x;
    float dh = 0.f;
    for (int s2 = 0; s2 < 32; s2++) {
        size_t row = (size_t)s2 * 64 + b;
        dh = fmaf(a2[row], Xo[row * 256 + h], dh);
    }
    for (int c = 0; c < C_; c++) {
        red[h] = dh * Wf[c * 256 + h];
        __syncthreads();
        for (int off = 128; off > 0; off >>= 1) {
            if (h < off) red[h] += red[h + off];
            __syncthreads();
        }
        if (h == 0) outp[b * C_ + c] = red[0] + bf[c];
        __syncthreads();
    }
}

// ---------------- launch ---------------------------------------------------
extern "C" void kernel_launch(void* const* d_in, const int* in_sizes, int n_in,
                              void* d_out, int out_size) {
    const int*   tokens = (const int*)d_in[0];
    const float* embed  = (const float*)d_in[1];
    const float* Wih_a  = (const float*)d_in[2];
    const float* Whh_a  = (const float*)d_in[3];
    const float* bih_a  = (const float*)d_in[4];
    const float* bhh_a  = (const float*)d_in[5];
    const float* WW_a   = (const float*)d_in[6];
    const float* b_a    = (const float*)d_in[7];
    const float* proj_a = (const float*)d_in[8];
    const float* Wih_e  = (const float*)d_in[9];
    const float* Whh_e  = (const float*)d_in[10];
    const float* bih_e  = (const float*)d_in[11];
    const float* bhh_e  = (const float*)d_in[12];
    const float* WW_e   = (const float*)d_in[13];
    const float* b_e    = (const float*)d_in[14];
    const float* proj_e = (const float*)d_in[15];
    const float* Wf     = (const float*)d_in[16];
    const float* bf     = (const float*)d_in[17];
    float* outp = (float*)d_out;

    void *xga_p, *io_p, *a1_p, *sent_p, *xge_p, *ioe_p, *a2_p;
    cudaGetSymbolAddress(&xga_p, g_xg_intra);
    cudaGetSymbolAddress(&io_p, g_intra_out);
    cudaGetSymbolAddress(&a1_p, g_a1);
    cudaGetSymbolAddress(&sent_p, g_sent);
    cudaGetSymbolAddress(&xge_p, g_xg_inter);
    cudaGetSymbolAddress(&ioe_p, g_inter_out);
    cudaGetSymbolAddress(&a2_p, g_a2);

    const int sm_g128  = (128 * 132 + 128 * 68) * 4;   // 102400
    const int sm_g256  = (128 * 260 + 128 * 68) * 4;   // 167936
    const int sm_attn  = (128 * 260 + 256 * 68) * 4;   // 202752
    const int sm_intra = (384 * 133 + 32 * 133) * 4;
    const int sm_inter = (384 * 133 + 2 * 132) * 4;
    cudaFuncSetAttribute(k_gemm_t<128>, cudaFuncAttributeMaxDynamicSharedMemorySize, sm_g128);
    cudaFuncSetAttribute(k_gemm_t<256>, cudaFuncAttributeMaxDynamicSharedMemorySize, sm_g256);
    cudaFuncSetAttribute(k_attn_t, cudaFuncAttributeMaxDynamicSharedMemorySize, sm_attn);
    cudaFuncSetAttribute(k_gru_intra, cudaFuncAttributeMaxDynamicSharedMemorySize, sm_intra);
    cudaFuncSetAttribute(k_gru_inter, cudaFuncAttributeMaxDynamicSharedMemorySize, sm_inter);

    // 1) intra input gates: gathered-embedding GEMM, rows = S*T*B = 131072
    k_gemm_t<128><<<dim3(1024, 6), 256, sm_g128>>>(tokens, embed, Wih_a, bih_a,
                                                   (float*)xga_p, 131072);
    // 2) intra biGRU (64 steps, one launch)
    k_gru_intra<<<128, 256, sm_intra>>>((float*)xga_p, Whh_a, bhh_a, (float*)io_p);
    // 3) word attention logits (fused tanh-proj-reduce)
    k_attn_t<<<1024, 256, sm_attn>>>((float*)io_p, WW_a, b_a, proj_a, (float*)a1_p);
    // 4) softmax over tokens
    k_softmax_t<<<8, 256>>>((float*)a1_p);
    // 5) sentence vectors
    k_sent<<<dim3(32, 8), 256>>>((float*)a1_p, (float*)io_p, (float*)sent_p);
    // 6) inter input gates: rows = S*B = 2048
    k_gemm_t<256><<<dim3(16, 6), 256, sm_g256>>>(nullptr, (float*)sent_p, Wih_e, bih_e,
                                                 (float*)xge_p, 2048);
    // 7) inter biGRU (32 steps, one launch)
    k_gru_inter<<<64, 256, sm_inter>>>((float*)xge_p, Whh_e, bhh_e, (float*)ioe_p);
    // 8) sentence attention logits (NO softmax)
    k_attn_t<<<16, 256, sm_attn>>>((float*)ioe_p, WW_e, b_e, proj_e, (float*)a2_p);
    // 9) doc vector + final linear
    k_doc_final<<<64, 256>>>((float*)a2_p, (float*)ioe_p, Wf, bf, outp);
}

// round 6
// speedup vs baseline: 2.8079x; 2.0889x over previous
#include <cuda_runtime.h>
#include <math.h>
#include <stdint.h>

#define S_  32
#define T_  64
#define B_  64
#define C_  5

// ---------------- scratch (device globals; no allocation) ----------------
__device__ float g_xg_intra[(size_t)2*S_*T_*B_*384]; // [dir][row(s,t,b)][384]
__device__ float g_intra_out[(size_t)S_*T_*B_*256];  // [s][t][b][256] fwd|bwd
__device__ float g_a1[S_*T_*B_];
__device__ float g_sent[S_*B_*256];
__device__ float g_xg_inter[2*S_*B_*384];            // [dir][row(s,b)][384]
__device__ float g_inter_out[S_*B_*256];
__device__ float g_a2[S_*B_];

__device__ __forceinline__ float sigm(float x) { return 1.f / (1.f + expf(-x)); }

__device__ __forceinline__ uint32_t f2tf(float f) {
    uint32_t o;
    asm("cvt.rna.tf32.f32 %0, %1;" : "=r"(o) : "f"(f));
    return o;
}

__device__ __forceinline__ void mma_tf32(float c[4],
                                         uint32_t a0, uint32_t a1, uint32_t a2, uint32_t a3,
                                         uint32_t b0, uint32_t b1) {
    asm volatile(
        "mma.sync.aligned.m16n8k8.row.col.f32.tf32.tf32.f32 "
        "{%0,%1,%2,%3}, {%4,%5,%6,%7}, {%8,%9}, {%0,%1,%2,%3};"
        : "+f"(c[0]), "+f"(c[1]), "+f"(c[2]), "+f"(c[3])
        : "r"(a0), "r"(a1), "r"(a2), "r"(a3), "r"(b0), "r"(b1));
}

// ================= K2 (tensor): input-gate GEMM, optionally gathered A ====
template<int KDIM>
__global__ __launch_bounds__(256) void k_gemm_t(const int* __restrict__ tokens,
                                                const float* __restrict__ A,
                                                const float* __restrict__ W,
                                                const float* __restrict__ bias,
                                                float* __restrict__ out,
                                                int nrows) {
    extern __shared__ uint32_t usm[];
    const int AST = KDIM + 4;
    uint32_t* As = usm;                  // 128 x AST
    uint32_t* Bs = usm + 128 * AST;      // 128 x 68
    __shared__ int toks[128];
    const int rb = blockIdx.x, cb = blockIdx.y;
    const int tid = threadIdx.x;
    const int lane = tid & 31, wid = tid >> 5;
    const int wm = wid >> 2, wn = wid & 3;   // warps: 2 (M) x 4 (N)
    const int grp = lane >> 2, t4 = lane & 3;

    if (tokens) {
        if (tid < 128) toks[tid] = tokens[rb * 128 + tid];
        __syncthreads();
    }
    for (int q = tid; q < 128 * (KDIM / 4); q += 256) {
        int r = q / (KDIM / 4), w4 = q % (KDIM / 4);
        const float* src = tokens ? (A + (size_t)toks[r] * KDIM + w4 * 4)
                                  : (A + (size_t)(rb * 128 + r) * KDIM + w4 * 4);
        float4 v = *(const float4*)src;
        uint4 u = make_uint4(f2tf(v.x), f2tf(v.y), f2tf(v.z), f2tf(v.w));
        *(uint4*)(As + r * AST + w4 * 4) = u;
    }

    float acc[4][4][4];
#pragma unroll
    for (int i = 0; i < 4; i++)
#pragma unroll
        for (int j = 0; j < 4; j++)
#pragma unroll
            for (int r = 0; r < 4; r++) acc[i][j][r] = 0.f;

    for (int kc = 0; kc < KDIM / 64; kc++) {
        __syncthreads();
        for (int q = tid; q < 128 * 16; q += 256) {
            int n = q >> 4, w4 = q & 15;
            float4 v = *(const float4*)(W + (size_t)(cb * 128 + n) * KDIM + kc * 64 + w4 * 4);
            uint4 u = make_uint4(f2tf(v.x), f2tf(v.y), f2tf(v.z), f2tf(v.w));
            *(uint4*)(Bs + n * 68 + w4 * 4) = u;
        }
        __syncthreads();
#pragma unroll
        for (int ks = 0; ks < 8; ks++) {
            const int k0 = kc * 64 + ks * 8;
            const int kb = ks * 8;
            uint32_t a[4][4], b[4][2];
#pragma unroll
            for (int i = 0; i < 4; i++) {
                int row = wm * 64 + i * 16 + grp;
                a[i][0] = As[row * AST + k0 + t4];
                a[i][1] = As[(row + 8) * AST + k0 + t4];
                a[i][2] = As[row * AST + k0 + t4 + 4];
                a[i][3] = As[(row + 8) * AST + k0 + t4 + 4];
            }
#pragma unroll
            for (int j = 0; j < 4; j++) {
                int n = wn * 32 + j * 8 + grp;
                b[j][0] = Bs[n * 68 + kb + t4];
                b[j][1] = Bs[n * 68 + kb + t4 + 4];
            }
#pragma unroll
            for (int i = 0; i < 4; i++)
#pragma unroll
                for (int j = 0; j < 4; j++)
                    mma_tf32(acc[i][j], a[i][0], a[i][1], a[i][2], a[i][3], b[j][0], b[j][1]);
        }
    }

    const int dir = (cb >= 3) ? 1 : 0;
#pragma unroll
    for (int i = 0; i < 4; i++) {
        int row = rb * 128 + wm * 64 + i * 16 + grp;
#pragma unroll
        for (int j = 0; j < 4; j++) {
            int col = cb * 128 + wn * 32 + j * 8 + 2 * t4;
            int g = col - dir * 384;
            float b0v = bias[col], b1v = bias[col + 1];
            float2 v0 = make_float2(acc[i][j][0] + b0v, acc[i][j][1] + b1v);
            float2 v1 = make_float2(acc[i][j][2] + b0v, acc[i][j][3] + b1v);
            *(float2*)&out[((size_t)dir * nrows + row) * 384 + g] = v0;
            *(float2*)&out[((size_t)dir * nrows + row + 8) * 384 + g] = v1;
        }
    }
}

// ========= attention (tensor): logits[row] = proj . tanh(X W + b) =========
__global__ __launch_bounds__(256) void k_attn_t(const float* __restrict__ X,
                                                const float* __restrict__ W,
                                                const float* __restrict__ bb,
                                                const float* __restrict__ proj,
                                                float* __restrict__ logits) {
    extern __shared__ uint32_t usm[];
    uint32_t* As = usm;                 // 128 x 260
    uint32_t* Bs = usm + 128 * 260;     // 256 x 68
    __shared__ float part_sm[128];
    const int rb = blockIdx.x;
    const int tid = threadIdx.x;
    const int lane = tid & 31, wid = tid >> 5;
    const int wm = wid >> 2, wn = wid & 3;
    const int grp = lane >> 2, t4 = lane & 3;

    for (int q = tid; q < 128 * 64; q += 256) {
        int r = q >> 6, w4 = q & 63;
        float4 v = *(const float4*)(X + (size_t)(rb * 128 + r) * 256 + w4 * 4);
        uint4 u = make_uint4(f2tf(v.x), f2tf(v.y), f2tf(v.z), f2tf(v.w));
        *(uint4*)(As + r * 260 + w4 * 4) = u;
    }
    if (tid < 128) part_sm[tid] = 0.f;

    float acc[4][8][4];
#pragma unroll
    for (int i = 0; i < 4; i++)
#pragma unroll
        for (int j = 0; j < 8; j++)
#pragma unroll
            for (int r = 0; r < 4; r++) acc[i][j][r] = 0.f;

    for (int kc = 0; kc < 4; kc++) {
        __syncthreads();
        for (int q = tid; q < 256 * 64; q += 256) {
            int n = q & 255, h = q >> 8;
            Bs[n * 68 + h] = f2tf(W[(size_t)(kc * 64 + h) * 256 + n]);
        }
        __syncthreads();
#pragma unroll
        for (int ks = 0; ks < 8; ks++) {
            const int k0 = kc * 64 + ks * 8;
            const int kb = ks * 8;
            uint32_t a[4][4], b[8][2];
#pragma unroll
            for (int i = 0; i < 4; i++) {
                int row = wm * 64 + i * 16 + grp;
                a[i][0] = As[row * 260 + k0 + t4];
                a[i][1] = As[(row + 8) * 260 + k0 + t4];
                a[i][2] = As[row * 260 + k0 + t4 + 4];
                a[i][3] = As[(row + 8) * 260 + k0 + t4 + 4];
            }
#pragma unroll
            for (int j = 0; j < 8; j++) {
                int n = wn * 64 + j * 8 + grp;
                b[j][0] = Bs[n * 68 + kb + t4];
                b[j][1] = Bs[n * 68 + kb + t4 + 4];
            }
#pragma unroll
            for (int i = 0; i < 4; i++)
#pragma unroll
                for (int j = 0; j < 8; j++)
                    mma_tf32(acc[i][j], a[i][0], a[i][1], a[i][2], a[i][3], b[j][0], b[j][1]);
        }
    }
    __syncthreads();

    float rsum[4][2];
#pragma unroll
    for (int i = 0; i < 4; i++) { rsum[i][0] = 0.f; rsum[i][1] = 0.f; }
#pragma unroll
    for (int j = 0; j < 8; j++) {
        int col = wn * 64 + j * 8 + 2 * t4;
        float pv0 = proj[col], pv1 = proj[col + 1];
        float bv0 = bb[col], bv1 = bb[col + 1];
#pragma unroll
        for (int i = 0; i < 4; i++) {
            rsum[i][0] += pv0 * tanhf(acc[i][j][0] + bv0) + pv1 * tanhf(acc[i][j][1] + bv1);
            rsum[i][1] += pv0 * tanhf(acc[i][j][2] + bv0) + pv1 * tanhf(acc[i][j][3] + bv1);
        }
    }
#pragma unroll
    for (int i = 0; i < 4; i++) {
#pragma unroll
        for (int sr = 0; sr < 2; sr++) {
            float v = rsum[i][sr];
            v += __shfl_xor_sync(0xffffffffu, v, 1);
            v += __shfl_xor_sync(0xffffffffu, v, 2);
            if (t4 == 0) atomicAdd(&part_sm[wm * 64 + i * 16 + sr * 8 + grp], v);
        }
    }
    __syncthreads();
    if (tid < 128) logits[(size_t)rb * 128 + tid] = part_sm[tid];
}

// ========== K3a: intra biGRU, tensor-core recurrence, 64 steps ============
// grid 128: dir = bx>>6, s = (bx>>1)&31, bhalf = bx&1 (32 batch rows/block)
// warp w owns hidden slice j in [16w,16w+16) for ALL 3 gates -> thread-local
// nonlinearity. h split hi+lo tf32 (2-term mma); Whh single tf32 in smem.
__global__ __launch_bounds__(256) void k_gru_intra_t(const float* __restrict__ xg,
                                                     const float* __restrict__ Whh,
                                                     const float* __restrict__ bhh,
                                                     float* __restrict__ out) {
    extern __shared__ uint32_t usm[];
    uint32_t* Ws = usm;                        // 384 x 132 (tf32 bits), [n][k]
    float* hsm = (float*)(usm + 384 * 132);    // 32 x 132 fp32
    const int bx = blockIdx.x;
    const int dir = bx >> 6, s = (bx >> 1) & 31, bh = bx & 1;
    const int b0 = bh * 32;
    const int tid = threadIdx.x;
    const int lane = tid & 31, w = tid >> 5;
    const int grp = lane >> 2, t4 = lane & 3;

    for (int idx = tid; idx < 384 * 128; idx += 256) {
        int n = idx >> 7, k = idx & 127;
        Ws[n * 132 + k] = f2tf(Whh[dir * 384 * 128 + idx]);
    }
    for (int idx = tid; idx < 32 * 132; idx += 256) hsm[idx] = 0.f;
    __syncthreads();

    const int j2 = 16 * w + 2 * t4;  // thread column base; +8*jj, +c
    float br[2][2], bz[2][2], bn[2][2];
#pragma unroll
    for (int jj = 0; jj < 2; jj++)
#pragma unroll
        for (int c = 0; c < 2; c++) {
            int j = j2 + 8 * jj + c;
            br[jj][c] = bhh[dir * 384 + j];
            bz[jj][c] = bhh[dir * 384 + 128 + j];
            bn[jj][c] = bhh[dir * 384 + 256 + j];
        }

    for (int tt = 0; tt < 64; tt++) {
        const int t = dir ? (63 - tt) : tt;
        const float* xgbase = xg + ((size_t)dir * 131072 + ((s * 64 + t) * 64 + b0)) * 384;

        // prefetch this step's xg (consumed in epilogue; covered by mma loop)
        float2 xr[4][2][3];  // [rowquad ri=2i+sr][jj][gate]
#pragma unroll
        for (int ri = 0; ri < 4; ri++) {
            const float* p = xgbase + (size_t)(grp + 8 * ri) * 384 + j2;
#pragma unroll
            for (int jj = 0; jj < 2; jj++) {
                xr[ri][jj][0] = *(const float2*)(p + 8 * jj);
                xr[ri][jj][1] = *(const float2*)(p + 128 + 8 * jj);
                xr[ri][jj][2] = *(const float2*)(p + 256 + 8 * jj);
            }
        }

        float acc[2][6][4];  // [m-tile][gate*2+jj][frag]
#pragma unroll
        for (int i = 0; i < 2; i++)
#pragma unroll
            for (int nt = 0; nt < 6; nt++)
#pragma unroll
                for (int r = 0; r < 4; r++) acc[i][nt][r] = 0.f;

#pragma unroll
        for (int ks = 0; ks < 16; ks++) {
            const int k0 = 8 * ks + t4;
            uint32_t ah[2][4], al[2][4];
#pragma unroll
            for (int i = 0; i < 2; i++) {
                float h0 = hsm[(16 * i + grp) * 132 + k0];
                float h1 = hsm[(16 * i + grp + 8) * 132 + k0];
                float h2 = hsm[(16 * i + grp) * 132 + k0 + 4];
                float h3 = hsm[(16 * i + grp + 8) * 132 + k0 + 4];
                ah[i][0] = f2tf(h0); al[i][0] = f2tf(h0 - __uint_as_float(ah[i][0]));
                ah[i][1] = f2tf(h1); al[i][1] = f2tf(h1 - __uint_as_float(ah[i][1]));
                ah[i][2] = f2tf(h2); al[i][2] = f2tf(h2 - __uint_as_float(ah[i][2]));
                ah[i][3] = f2tf(h3); al[i][3] = f2tf(h3 - __uint_as_float(ah[i][3]));
            }
#pragma unroll
            for (int nt = 0; nt < 6; nt++) {
                int n = 128 * (nt >> 1) + 16 * w + 8 * (nt & 1) + grp;
                uint32_t brg0 = Ws[n * 132 + 8 * ks + t4];
                uint32_t brg1 = Ws[n * 132 + 8 * ks + t4 + 4];
                mma_tf32(acc[0][nt], ah[0][0], ah[0][1], ah[0][2], ah[0][3], brg0, brg1);
                mma_tf32(acc[0][nt], al[0][0], al[0][1], al[0][2], al[0][3], brg0, brg1);
                mma_tf32(acc[1][nt], ah[1][0], ah[1][1], ah[1][2], ah[1][3], brg0, brg1);
                mma_tf32(acc[1][nt], al[1][0], al[1][1], al[1][2], al[1][3], brg0, brg1);
            }
        }

        // epilogue: thread-local gates; stash h_new, write out
        float hn[2][2][2][2];  // [i][sr][jj][c]
#pragma unroll
        for (int i = 0; i < 2; i++)
#pragma unroll
            for (int sr = 0; sr < 2; sr++) {
                int ri = 2 * i + sr;
                int row = 16 * i + 8 * sr + grp;
#pragma unroll
                for (int jj = 0; jj < 2; jj++) {
                    float2 ho = *(const float2*)&hsm[row * 132 + j2 + 8 * jj];
                    float hoa0 = ho.x, hoa1 = ho.y;
                    float r0 = sigm(xr[ri][jj][0].x + acc[i][jj][2 * sr] + br[jj][0]);
                    float r1 = sigm(xr[ri][jj][0].y + acc[i][jj][2 * sr + 1] + br[jj][1]);
                    float z0 = sigm(xr[ri][jj][1].x + acc[i][2 + jj][2 * sr] + bz[jj][0]);
                    float z1 = sigm(xr[ri][jj][1].y + acc[i][2 + jj][2 * sr + 1] + bz[jj][1]);
                    float n0 = tanhf(xr[ri][jj][2].x + r0 * (acc[i][4 + jj][2 * sr] + bn[jj][0]));
                    float n1 = tanhf(xr[ri][jj][2].y + r1 * (acc[i][4 + jj][2 * sr + 1] + bn[jj][1]));
                    float h0 = (1.f - z0) * n0 + z0 * hoa0;
                    float h1 = (1.f - z1) * n1 + z1 * hoa1;
                    hn[i][sr][jj][0] = h0;
                    hn[i][sr][jj][1] = h1;
                    *(float2*)&out[(((size_t)(s * 64 + t)) * 64 + b0 + row) * 256 +
                                   dir * 128 + j2 + 8 * jj] = make_float2(h0, h1);
                }
            }
        __syncthreads();
#pragma unroll
        for (int i = 0; i < 2; i++)
#pragma unroll
            for (int sr = 0; sr < 2; sr++) {
                int row = 16 * i + 8 * sr + grp;
#pragma unroll
                for (int jj = 0; jj < 2; jj++)
                    *(float2*)&hsm[row * 132 + j2 + 8 * jj] =
                        make_float2(hn[i][sr][jj][0], hn[i][sr][jj][1]);
            }
        __syncthreads();
    }
}

// ---------------- K3b: inter biGRU, all 32 steps, one launch --------------
__global__ void k_gru_inter(const float* __restrict__ xg,
                            const float* __restrict__ Whh,
                            const float* __restrict__ bhh,
                            float* __restrict__ out) {
    extern __shared__ float sm[];
    float* Ws = sm;              // 384*133
    float* hs = sm + 384 * 133;  // 2*132
    const int bx = blockIdx.x;
    const int dir = bx >> 5;
    const int b0 = (bx & 31) * 2;
    const int tid = threadIdx.x;
    const int bl = tid >> 7;
    const int j = tid & 127;

    for (int idx = tid; idx < 384 * 128; idx += 256) {
        int row = idx >> 7, k = idx & 127;
        Ws[row * 133 + k] = Whh[dir * 384 * 128 + idx];
    }
    for (int idx = tid; idx < 2 * 132; idx += 256) hs[idx] = 0.f;
    __syncthreads();

    const float br = bhh[dir * 384 + j];
    const float bz = bhh[dir * 384 + 128 + j];
    const float bn = bhh[dir * 384 + 256 + j];

    for (int tt = 0; tt < 32; tt++) {
        const int sstep = dir ? (31 - tt) : tt;
        float ar = 0.f, az = 0.f, an = 0.f;
#pragma unroll 4
        for (int k = 0; k < 128; k++) {
            float hv = hs[bl * 132 + k];
            int ro = j * 133 + k;
            ar = fmaf(hv, Ws[ro], ar);
            az = fmaf(hv, Ws[ro + 128 * 133], az);
            an = fmaf(hv, Ws[ro + 256 * 133], an);
        }
        const int b = b0 + bl;
        const float* xr = xg + (((size_t)dir * 32 + sstep) * 64 + b) * 384;
        float r = sigm(xr[j] + ar + br);
        float z = sigm(xr[128 + j] + az + bz);
        float n = tanhf(xr[256 + j] + r * (an + bn));
        float ho = hs[bl * 132 + j];
        float hv2 = (1.f - z) * n + z * ho;
        out[((size_t)sstep * 64 + b) * 256 + dir * 128 + j] = hv2;
        __syncthreads();
        hs[bl * 132 + j] = hv2;
        __syncthreads();
    }
}

// ---------------- softmax over t, in place --------------------------------
__global__ void k_softmax_t(float* __restrict__ a) {
    int gid = blockIdx.x * blockDim.x + threadIdx.x;
    if (gid >= S_ * B_) return;
    int s = gid >> 6, b = gid & 63;
    size_t base = (size_t)s * 4096 + b;
    float mx = -1e30f;
    for (int t = 0; t < 64; t++) mx = fmaxf(mx, a[base + t * 64]);
    float sum = 0.f;
    for (int t = 0; t < 64; t++) sum += expf(a[base + t * 64] - mx);
    float inv = 1.f / sum;
    for (int t = 0; t < 64; t++) a[base + t * 64] = expf(a[base + t * 64] - mx) * inv;
}

// ---------------- sentence vectors: sum_t a1 * X ---------------------------
__global__ void k_sent(const float* __restrict__ a1,
                       const float* __restrict__ X,
                       float* __restrict__ sent) {
    const int s = blockIdx.x, bg = blockIdx.y;
    const int h = threadIdx.x;
    float acc[8];
#pragma unroll
    for (int ib = 0; ib < 8; ib++) acc[ib] = 0.f;
    for (int t = 0; t < 64; t++) {
#pragma unroll
        for (int ib = 0; ib < 8; ib++) {
            int b = bg * 8 + ib;
            size_t row = (size_t)s * 4096 + (size_t)t * 64 + b;
            acc[ib] = fmaf(a1[row], X[row * 256 + h], acc[ib]);
        }
    }
#pragma unroll
    for (int ib = 0; ib < 8; ib++)
        sent[((size_t)s * 64 + bg * 8 + ib) * 256 + h] = acc[ib];
}

// ---------------- doc vector + final linear --------------------------------
__global__ void k_doc_final(const float* __restrict__ a2,
                            const float* __restrict__ Xo,
                            const float* __restrict__ Wf,
                            const float* __restrict__ bf,
                            float* __restrict__ outp) {
    __shared__ float red[256];
    const int b = blockIdx.x, h = threadIdx.x;
    float dh = 0.f;
    for (int s2 = 0; s2 < 32; s2++) {
        size_t row = (size_t)s2 * 64 + b;
        dh = fmaf(a2[row], Xo[row * 256 + h], dh);
    }
    for (int c = 0; c < C_; c++) {
        red[h] = dh * Wf[c * 256 + h];
        __syncthreads();
        for (int off = 128; off > 0; off >>= 1) {
            if (h < off) red[h] += red[h + off];
            __syncthreads();
        }
        if (h == 0) outp[b * C_ + c] = red[0] + bf[c];
        __syncthreads();
    }
}

// ---------------- launch ---------------------------------------------------
extern "C" void kernel_launch(void* const* d_in, const int* in_sizes, int n_in,
                              void* d_out, int out_size) {
    const int*   tokens = (const int*)d_in[0];
    const float* embed  = (const float*)d_in[1];
    const float* Wih_a  = (const float*)d_in[2];
    const float* Whh_a  = (const float*)d_in[3];
    const float* bih_a  = (const float*)d_in[4];
    const float* bhh_a  = (const float*)d_in[5];
    const float* WW_a   = (const float*)d_in[6];
    const float* b_a    = (const float*)d_in[7];
    const float* proj_a = (const float*)d_in[8];
    const float* Wih_e  = (const float*)d_in[9];
    const float* Whh_e  = (const float*)d_in[10];
    const float* bih_e  = (const float*)d_in[11];
    const float* bhh_e  = (const float*)d_in[12];
    const float* WW_e   = (const float*)d_in[13];
    const float* b_e    = (const float*)d_in[14];
    const float* proj_e = (const float*)d_in[15];
    const float* Wf     = (const float*)d_in[16];
    const float* bf     = (const float*)d_in[17];
    float* outp = (float*)d_out;

    void *xga_p, *io_p, *a1_p, *sent_p, *xge_p, *ioe_p, *a2_p;
    cudaGetSymbolAddress(&xga_p, g_xg_intra);
    cudaGetSymbolAddress(&io_p, g_intra_out);
    cudaGetSymbolAddress(&a1_p, g_a1);
    cudaGetSymbolAddress(&sent_p, g_sent);
    cudaGetSymbolAddress(&xge_p, g_xg_inter);
    cudaGetSymbolAddress(&ioe_p, g_inter_out);
    cudaGetSymbolAddress(&a2_p, g_a2);

    const int sm_g128   = (128 * 132 + 128 * 68) * 4;
    const int sm_g256   = (128 * 260 + 128 * 68) * 4;
    const int sm_attn   = (128 * 260 + 256 * 68) * 4;
    const int sm_intra  = (384 * 132 + 32 * 132) * 4;   // 219648
    const int sm_inter  = (384 * 133 + 2 * 132) * 4;
    cudaFuncSetAttribute(k_gemm_t<128>, cudaFuncAttributeMaxDynamicSharedMemorySize, sm_g128);
    cudaFuncSetAttribute(k_gemm_t<256>, cudaFuncAttributeMaxDynamicSharedMemorySize, sm_g256);
    cudaFuncSetAttribute(k_attn_t, cudaFuncAttributeMaxDynamicSharedMemorySize, sm_attn);
    cudaFuncSetAttribute(k_gru_intra_t, cudaFuncAttributeMaxDynamicSharedMemorySize, sm_intra);
    cudaFuncSetAttribute(k_gru_inter, cudaFuncAttributeMaxDynamicSharedMemorySize, sm_inter);

    // 1) intra input gates: gathered-embedding GEMM, rows = S*T*B = 131072
    k_gemm_t<128><<<dim3(1024, 6), 256, sm_g128>>>(tokens, embed, Wih_a, bih_a,
                                                   (float*)xga_p, 131072);
    // 2) intra biGRU (tensor-core recurrence, 64 steps, one launch)
    k_gru_intra_t<<<128, 256, sm_intra>>>((float*)xga_p, Whh_a, bhh_a, (float*)io_p);
    // 3) word attention logits (fused tanh-proj-reduce)
    k_attn_t<<<1024, 256, sm_attn>>>((float*)io_p, WW_a, b_a, proj_a, (float*)a1_p);
    // 4) softmax over tokens
    k_softmax_t<<<8, 256>>>((float*)a1_p);
    // 5) sentence vectors
    k_sent<<<dim3(32, 8), 256>>>((float*)a1_p, (float*)io_p, (float*)sent_p);
    // 6) inter input gates: rows = S*B = 2048
    k_gemm_t<256><<<dim3(16, 6), 256, sm_g256>>>(nullptr, (float*)sent_p, Wih_e, bih_e,
                                                 (float*)xge_p, 2048);
    // 7) inter biGRU (32 steps, one launch)
    k_gru_inter<<<64, 256, sm_inter>>>((float*)xge_p, Whh_e, bhh_e, (float*)ioe_p);
    // 8) sentence attention logits (NO softmax)
    k_attn_t<<<16, 256, sm_attn>>>((float*)ioe_p, WW_e, b_e, proj_e, (float*)a2_p);
    // 9) doc vector + final linear
    k_doc_final<<<64, 256>>>((float*)a2_p, (float*)ioe_p, Wf, bf, outp);
}

// round 7
// speedup vs baseline: 2.9342x; 1.0450x over previous
#include <cuda_runtime.h>
#include <math.h>
#include <stdint.h>

#define S_  32
#define T_  64
#define B_  64
#define C_  5

// ---------------- scratch (device globals; no allocation) ----------------
__device__ float g_xg_intra[(size_t)2*S_*T_*B_*384]; // [dir][row(s,t,b)][384]
__device__ float g_intra_out[(size_t)S_*T_*B_*256];  // [s][t][b][256] fwd|bwd
__device__ float g_a1p[2*S_*T_*B_];                  // 2 partial planes
__device__ float g_sent[S_*B_*256];
__device__ float g_xg_inter[2*S_*B_*384];            // [dir][row(s,b)][384]
__device__ float g_inter_out[S_*B_*256];
__device__ float g_a2p[2*S_*B_];
__device__ uint32_t g_wt[2*256*256];                 // WW_a, WW_e transposed tf32

__device__ __forceinline__ float sigm(float x) { return 1.f / (1.f + expf(-x)); }

__device__ __forceinline__ uint32_t f2tf(float f) {
    uint32_t o;
    asm("cvt.rna.tf32.f32 %0, %1;" : "=r"(o) : "f"(f));
    return o;
}

__device__ __forceinline__ void mma_tf32(float c[4],
                                         uint32_t a0, uint32_t a1, uint32_t a2, uint32_t a3,
                                         uint32_t b0, uint32_t b1) {
    asm volatile(
        "mma.sync.aligned.m16n8k8.row.col.f32.tf32.tf32.f32 "
        "{%0,%1,%2,%3}, {%4,%5,%6,%7}, {%8,%9}, {%0,%1,%2,%3};"
        : "+f"(c[0]), "+f"(c[1]), "+f"(c[2]), "+f"(c[3])
        : "r"(a0), "r"(a1), "r"(a2), "r"(a3), "r"(b0), "r"(b1));
}

// ---- prep: transpose + tf32-convert attention weight matrices ------------
__global__ void k_prep_wt(const float* __restrict__ Wa,
                          const float* __restrict__ We,
                          uint32_t* __restrict__ wt) {
    int idx = blockIdx.x * 256 + threadIdx.x;       // 0..65535
    const float* W = blockIdx.y ? We : Wa;
    int n = idx >> 8, h = idx & 255;
    wt[blockIdx.y * 65536 + n * 256 + h] = f2tf(W[h * 256 + n]);
}

// ============ unified tensor GEMM: 64-row blocks, 2 blocks/SM =============
// C[row, col] = sum_k A[row,k] * B[col,k]
// ATTN=false: out[((dir*nrows+row)*384 + (col - 384*dir)] = C + bias[col]
// ATTN=true : out[cb*nrows + row] = sum_col proj[col]*tanh(C + bias[col])
template<int KDIM, int NCOLS, bool ATTN, bool PRECONV>
__global__ __launch_bounds__(256, 2) void k_gemm2(const int* __restrict__ tokens,
                                                  const float* __restrict__ A,
                                                  const void* __restrict__ Wv,
                                                  const float* __restrict__ bias,
                                                  const float* __restrict__ proj,
                                                  float* __restrict__ out,
                                                  int nrows) {
    constexpr int AST = KDIM + 4;
    constexpr int JT = NCOLS / 32;       // n-tiles per warp
    constexpr int WNC = NCOLS / 4;       // cols per N-warp
    extern __shared__ uint32_t usm[];
    uint32_t* As = usm;                  // 64 x AST
    uint32_t* Bs = usm + 64 * AST;       // NCOLS x 68 (64-k chunk)
    __shared__ int toks[64];
    __shared__ float part_sm[4][65];
    const int rb = blockIdx.x, cb = blockIdx.y;
    const int tid = threadIdx.x;
    const int lane = tid & 31, wid = tid >> 5;
    const int wm = wid >> 2, wn = wid & 3;   // 2 (M) x 4 (N)
    const int grp = lane >> 2, t4 = lane & 3;

    if (tokens) {
        if (tid < 64) toks[tid] = tokens[rb * 64 + tid];
        __syncthreads();
    }
    // A tile: 64 rows x KDIM, tf32, resident for whole kernel
    for (int q = tid; q < 64 * (KDIM / 4); q += 256) {
        int r = q / (KDIM / 4), w4 = q % (KDIM / 4);
        const float* src = tokens ? (A + (size_t)toks[r] * KDIM + w4 * 4)
                                  : (A + (size_t)(rb * 64 + r) * KDIM + w4 * 4);
        float4 v = *(const float4*)src;
        uint4 u = make_uint4(f2tf(v.x), f2tf(v.y), f2tf(v.z), f2tf(v.w));
        *(uint4*)(As + r * AST + w4 * 4) = u;
    }

    float acc[2][JT][4];
#pragma unroll
    for (int i = 0; i < 2; i++)
#pragma unroll
        for (int j = 0; j < JT; j++)
#pragma unroll
            for (int r = 0; r < 4; r++) acc[i][j][r] = 0.f;

    for (int kc = 0; kc < KDIM / 64; kc++) {
        __syncthreads();
        if (PRECONV) {
            const uint32_t* Wt = (const uint32_t*)Wv;
            for (int q = tid; q < NCOLS * 16; q += 256) {
                int n = q >> 4, w4 = q & 15;
                uint4 u = *(const uint4*)(Wt + (size_t)(cb * NCOLS + n) * KDIM + kc * 64 + w4 * 4);
                *(uint4*)(Bs + n * 68 + w4 * 4) = u;
            }
        } else {
            const float* W = (const float*)Wv;
            for (int q = tid; q < NCOLS * 16; q += 256) {
                int n = q >> 4, w4 = q & 15;
                float4 v = *(const float4*)(W + (size_t)(cb * NCOLS + n) * KDIM + kc * 64 + w4 * 4);
                uint4 u = make_uint4(f2tf(v.x), f2tf(v.y), f2tf(v.z), f2tf(v.w));
                *(uint4*)(Bs + n * 68 + w4 * 4) = u;
            }
        }
        __syncthreads();
#pragma unroll
        for (int ks = 0; ks < 8; ks++) {
            const int k0 = kc * 64 + ks * 8;
            const int kb = ks * 8;
            uint32_t a[2][4], b[JT][2];
#pragma unroll
            for (int i = 0; i < 2; i++) {
                int row = wm * 32 + i * 16 + grp;
                a[i][0] = As[row * AST + k0 + t4];
                a[i][1] = As[(row + 8) * AST + k0 + t4];
                a[i][2] = As[row * AST + k0 + t4 + 4];
                a[i][3] = As[(row + 8) * AST + k0 + t4 + 4];
            }
#pragma unroll
            for (int j = 0; j < JT; j++) {
                int n = wn * WNC + j * 8 + grp;
                b[j][0] = Bs[n * 68 + kb + t4];
                b[j][1] = Bs[n * 68 + kb + t4 + 4];
            }
#pragma unroll
            for (int i = 0; i < 2; i++)
#pragma unroll
                for (int j = 0; j < JT; j++)
                    mma_tf32(acc[i][j], a[i][0], a[i][1], a[i][2], a[i][3], b[j][0], b[j][1]);
        }
    }

    if (!ATTN) {
        // gate-GEMM epilogue: col -> (dir, g), +bias
#pragma unroll
        for (int i = 0; i < 2; i++) {
            int row = rb * 64 + wm * 32 + i * 16 + grp;
#pragma unroll
            for (int j = 0; j < JT; j++) {
                int col = cb * NCOLS + wn * WNC + j * 8 + 2 * t4;
                int dir = (col >= 384) ? 1 : 0;
                int g = col - dir * 384;
                float b0v = bias[col], b1v = bias[col + 1];
                float2 v0 = make_float2(acc[i][j][0] + b0v, acc[i][j][1] + b1v);
                float2 v1 = make_float2(acc[i][j][2] + b0v, acc[i][j][3] + b1v);
                *(float2*)&out[((size_t)dir * nrows + row) * 384 + g] = v0;
                *(float2*)&out[((size_t)dir * nrows + row + 8) * 384 + g] = v1;
            }
        }
    } else {
        // fused attention epilogue: partial sum over this block's 128 cols
        float rsum[2][2];
#pragma unroll
        for (int i = 0; i < 2; i++) { rsum[i][0] = 0.f; rsum[i][1] = 0.f; }
#pragma unroll
        for (int j = 0; j < JT; j++) {
            int col = cb * NCOLS + wn * WNC + j * 8 + 2 * t4;
            float pv0 = proj[col], pv1 = proj[col + 1];
            float bv0 = bias[col], bv1 = bias[col + 1];
#pragma unroll
            for (int i = 0; i < 2; i++) {
                rsum[i][0] += pv0 * tanhf(acc[i][j][0] + bv0) + pv1 * tanhf(acc[i][j][1] + bv1);
                rsum[i][1] += pv0 * tanhf(acc[i][j][2] + bv0) + pv1 * tanhf(acc[i][j][3] + bv1);
            }
        }
#pragma unroll
        for (int i = 0; i < 2; i++)
#pragma unroll
            for (int sr = 0; sr < 2; sr++) {
                float v = rsum[i][sr];
                v += __shfl_xor_sync(0xffffffffu, v, 1);
                v += __shfl_xor_sync(0xffffffffu, v, 2);
                if (t4 == 0) part_sm[wn][wm * 32 + i * 16 + sr * 8 + grp] = v;
            }
        __syncthreads();
        if (tid < 64)
            out[(size_t)cb * nrows + rb * 64 + tid] =
                part_sm[0][tid] + part_sm[1][tid] + part_sm[2][tid] + part_sm[3][tid];
    }
}

// ========== K3a: intra biGRU, tensor-core recurrence, 64 steps ============
__global__ __launch_bounds__(256) void k_gru_intra_t(const float* __restrict__ xg,
                                                     const float* __restrict__ Whh,
                                                     const float* __restrict__ bhh,
                                                     float* __restrict__ out) {
    extern __shared__ uint32_t usm[];
    uint32_t* Ws = usm;                        // 384 x 132 tf32 [n][k]
    float* hsm = (float*)(usm + 384 * 132);    // 32 x 132 fp32
    const int bx = blockIdx.x;
    const int dir = bx >> 6, s = (bx >> 1) & 31, bh = bx & 1;
    const int b0 = bh * 32;
    const int tid = threadIdx.x;
    const int lane = tid & 31, w = tid >> 5;
    const int grp = lane >> 2, t4 = lane & 3;

    for (int idx = tid; idx < 384 * 128; idx += 256) {
        int n = idx >> 7, k = idx & 127;
        Ws[n * 132 + k] = f2tf(Whh[dir * 384 * 128 + idx]);
    }
    for (int idx = tid; idx < 32 * 132; idx += 256) hsm[idx] = 0.f;
    __syncthreads();

    const int j2 = 16 * w + 2 * t4;
    float br[2][2], bz[2][2], bn[2][2];
#pragma unroll
    for (int jj = 0; jj < 2; jj++)
#pragma unroll
        for (int c = 0; c < 2; c++) {
            int j = j2 + 8 * jj + c;
            br[jj][c] = bhh[dir * 384 + j];
            bz[jj][c] = bhh[dir * 384 + 128 + j];
            bn[jj][c] = bhh[dir * 384 + 256 + j];
        }

    for (int tt = 0; tt < 64; tt++) {
        const int t = dir ? (63 - tt) : tt;
        const float* xgbase = xg + ((size_t)dir * 131072 + ((s * 64 + t) * 64 + b0)) * 384;

        float2 xr[4][2][3];
#pragma unroll
        for (int ri = 0; ri < 4; ri++) {
            const float* p = xgbase + (size_t)(grp + 8 * ri) * 384 + j2;
#pragma unroll
            for (int jj = 0; jj < 2; jj++) {
                xr[ri][jj][0] = *(const float2*)(p + 8 * jj);
                xr[ri][jj][1] = *(const float2*)(p + 128 + 8 * jj);
                xr[ri][jj][2] = *(const float2*)(p + 256 + 8 * jj);
            }
        }

        float acc[2][6][4];
#pragma unroll
        for (int i = 0; i < 2; i++)
#pragma unroll
            for (int nt = 0; nt < 6; nt++)
#pragma unroll
                for (int r = 0; r < 4; r++) acc[i][nt][r] = 0.f;

#pragma unroll
        for (int ks = 0; ks < 16; ks++) {
            const int k0 = 8 * ks + t4;
            uint32_t ah[2][4], al[2][4];
#pragma unroll
            for (int i = 0; i < 2; i++) {
                float h0 = hsm[(16 * i + grp) * 132 + k0];
                float h1 = hsm[(16 * i + grp + 8) * 132 + k0];
                float h2 = hsm[(16 * i + grp) * 132 + k0 + 4];
                float h3 = hsm[(16 * i + grp + 8) * 132 + k0 + 4];
                ah[i][0] = f2tf(h0); al[i][0] = f2tf(h0 - __uint_as_float(ah[i][0]));
                ah[i][1] = f2tf(h1); al[i][1] = f2tf(h1 - __uint_as_float(ah[i][1]));
                ah[i][2] = f2tf(h2); al[i][2] = f2tf(h2 - __uint_as_float(ah[i][2]));
                ah[i][3] = f2tf(h3); al[i][3] = f2tf(h3 - __uint_as_float(ah[i][3]));
            }
#pragma unroll
            for (int nt = 0; nt < 6; nt++) {
                int n = 128 * (nt >> 1) + 16 * w + 8 * (nt & 1) + grp;
                uint32_t brg0 = Ws[n * 132 + 8 * ks + t4];
                uint32_t brg1 = Ws[n * 132 + 8 * ks + t4 + 4];
                mma_tf32(acc[0][nt], ah[0][0], ah[0][1], ah[0][2], ah[0][3], brg0, brg1);
                mma_tf32(acc[0][nt], al[0][0], al[0][1], al[0][2], al[0][3], brg0, brg1);
                mma_tf32(acc[1][nt], ah[1][0], ah[1][1], ah[1][2], ah[1][3], brg0, brg1);
                mma_tf32(acc[1][nt], al[1][0], al[1][1], al[1][2], al[1][3], brg0, brg1);
            }
        }

        float hn[2][2][2][2];
#pragma unroll
        for (int i = 0; i < 2; i++)
#pragma unroll
            for (int sr = 0; sr < 2; sr++) {
                int ri = 2 * i + sr;
                int row = 16 * i + 8 * sr + grp;
#pragma unroll
                for (int jj = 0; jj < 2; jj++) {
                    float2 ho = *(const float2*)&hsm[row * 132 + j2 + 8 * jj];
                    float r0 = sigm(xr[ri][jj][0].x + acc[i][jj][2 * sr] + br[jj][0]);
                    float r1 = sigm(xr[ri][jj][0].y + acc[i][jj][2 * sr + 1] + br[jj][1]);
                    float z0 = sigm(xr[ri][jj][1].x + acc[i][2 + jj][2 * sr] + bz[jj][0]);
                    float z1 = sigm(xr[ri][jj][1].y + acc[i][2 + jj][2 * sr + 1] + bz[jj][1]);
                    float n0 = tanhf(xr[ri][jj][2].x + r0 * (acc[i][4 + jj][2 * sr] + bn[jj][0]));
                    float n1 = tanhf(xr[ri][jj][2].y + r1 * (acc[i][4 + jj][2 * sr + 1] + bn[jj][1]));
                    float h0 = (1.f - z0) * n0 + z0 * ho.x;
                    float h1 = (1.f - z1) * n1 + z1 * ho.y;
                    hn[i][sr][jj][0] = h0;
                    hn[i][sr][jj][1] = h1;
                    *(float2*)&out[(((size_t)(s * 64 + t)) * 64 + b0 + row) * 256 +
                                   dir * 128 + j2 + 8 * jj] = make_float2(h0, h1);
                }
            }
        __syncthreads();
#pragma unroll
        for (int i = 0; i < 2; i++)
#pragma unroll
            for (int sr = 0; sr < 2; sr++) {
                int row = 16 * i + 8 * sr + grp;
#pragma unroll
                for (int jj = 0; jj < 2; jj++)
                    *(float2*)&hsm[row * 132 + j2 + 8 * jj] =
                        make_float2(hn[i][sr][jj][0], hn[i][sr][jj][1]);
            }
        __syncthreads();
    }
}

// ---------------- K3b: inter biGRU, all 32 steps, one launch --------------
__global__ void k_gru_inter(const float* __restrict__ xg,
                            const float* __restrict__ Whh,
                            const float* __restrict__ bhh,
                            float* __restrict__ out) {
    extern __shared__ float sm[];
    float* Ws = sm;              // 384*133
    float* hs = sm + 384 * 133;  // 2*132
    const int bx = blockIdx.x;
    const int dir = bx >> 5;
    const int b0 = (bx & 31) * 2;
    const int tid = threadIdx.x;
    const int bl = tid >> 7;
    const int j = tid & 127;

    for (int idx = tid; idx < 384 * 128; idx += 256) {
        int row = idx >> 7, k = idx & 127;
        Ws[row * 133 + k] = Whh[dir * 384 * 128 + idx];
    }
    for (int idx = tid; idx < 2 * 132; idx += 256) hs[idx] = 0.f;
    __syncthreads();

    const float br = bhh[dir * 384 + j];
    const float bz = bhh[dir * 384 + 128 + j];
    const float bn = bhh[dir * 384 + 256 + j];

    for (int tt = 0; tt < 32; tt++) {
        const int sstep = dir ? (31 - tt) : tt;
        float ar = 0.f, az = 0.f, an = 0.f;
#pragma unroll 4
        for (int k = 0; k < 128; k++) {
            float hv = hs[bl * 132 + k];
            int ro = j * 133 + k;
            ar = fmaf(hv, Ws[ro], ar);
            az = fmaf(hv, Ws[ro + 128 * 133], az);
            an = fmaf(hv, Ws[ro + 256 * 133], an);
        }
        const int b = b0 + bl;
        const float* xr = xg + (((size_t)dir * 32 + sstep) * 64 + b) * 384;
        float r = sigm(xr[j] + ar + br);
        float z = sigm(xr[128 + j] + az + bz);
        float n = tanhf(xr[256 + j] + r * (an + bn));
        float ho = hs[bl * 132 + j];
        float hv2 = (1.f - z) * n + z * ho;
        out[((size_t)sstep * 64 + b) * 256 + dir * 128 + j] = hv2;
        __syncthreads();
        hs[bl * 132 + j] = hv2;
        __syncthreads();
    }
}

// ------- softmax over t (sums 2 partial planes, writes plane 0) -----------
__global__ void k_softmax_t(float* __restrict__ a) {
    const int NP = S_ * T_ * B_;
    int gid = blockIdx.x * blockDim.x + threadIdx.x;
    if (gid >= S_ * B_) return;
    int s = gid >> 6, b = gid & 63;
    size_t base = (size_t)s * 4096 + b;
    float mx = -1e30f;
    for (int t = 0; t < 64; t++) {
        float v = a[base + t * 64] + a[NP + base + t * 64];
        mx = fmaxf(mx, v);
    }
    float sum = 0.f;
    for (int t = 0; t < 64; t++) {
        float v = a[base + t * 64] + a[NP + base + t * 64];
        sum += expf(v - mx);
    }
    float inv = 1.f / sum;
    for (int t = 0; t < 64; t++) {
        float v = a[base + t * 64] + a[NP + base + t * 64];
        a[base + t * 64] = expf(v - mx) * inv;
    }
}

// ---------------- sentence vectors: sum_t a1 * X ---------------------------
__global__ void k_sent(const float* __restrict__ a1,
                       const float* __restrict__ X,
                       float* __restrict__ sent) {
    const int s = blockIdx.x, bg = blockIdx.y;
    const int h = threadIdx.x;
    float acc[8];
#pragma unroll
    for (int ib = 0; ib < 8; ib++) acc[ib] = 0.f;
    for (int t = 0; t < 64; t++) {
#pragma unroll
        for (int ib = 0; ib < 8; ib++) {
            int b = bg * 8 + ib;
            size_t row = (size_t)s * 4096 + (size_t)t * 64 + b;
            acc[ib] = fmaf(a1[row], X[row * 256 + h], acc[ib]);
        }
    }
#pragma unroll
    for (int ib = 0; ib < 8; ib++)
        sent[((size_t)s * 64 + bg * 8 + ib) * 256 + h] = acc[ib];
}

// --------- doc vector + final linear (sums 2 partial a2 planes) -----------
__global__ void k_doc_final(const float* __restrict__ a2,
                            const float* __restrict__ Xo,
                            const float* __restrict__ Wf,
                            const float* __restrict__ bf,
                            float* __restrict__ outp) {
    __shared__ float red[256];
    const int b = blockIdx.x, h = threadIdx.x;
    float dh = 0.f;
    for (int s2 = 0; s2 < 32; s2++) {
        size_t row = (size_t)s2 * 64 + b;
        float av = a2[row] + a2[S_ * B_ + row];
        dh = fmaf(av, Xo[row * 256 + h], dh);
    }
    for (int c = 0; c < C_; c++) {
        red[h] = dh * Wf[c * 256 + h];
        __syncthreads();
        for (int off = 128; off > 0; off >>= 1) {
            if (h < off) red[h] += red[h + off];
            __syncthreads();
        }
        if (h == 0) outp[b * C_ + c] = red[0] + bf[c];
        __syncthreads();
    }
}

// ---------------- launch ---------------------------------------------------
extern "C" void kernel_launch(void* const* d_in, const int* in_sizes, int n_in,
                              void* d_out, int out_size) {
    const int*   tokens = (const int*)d_in[0];
    const float* embed  = (const float*)d_in[1];
    const float* Wih_a  = (const float*)d_in[2];
    const float* Whh_a  = (const float*)d_in[3];
    const float* bih_a  = (const float*)d_in[4];
    const float* bhh_a  = (const float*)d_in[5];
    const float* WW_a   = (const float*)d_in[6];
    const float* b_a    = (const float*)d_in[7];
    const float* proj_a = (const float*)d_in[8];
    const float* Wih_e  = (const float*)d_in[9];
    const float* Whh_e  = (const float*)d_in[10];
    const float* bih_e  = (const float*)d_in[11];
    const float* bhh_e  = (const float*)d_in[12];
    const float* WW_e   = (const float*)d_in[13];
    const float* b_e    = (const float*)d_in[14];
    const float* proj_e = (const float*)d_in[15];
    const float* Wf     = (const float*)d_in[16];
    const float* bf     = (const float*)d_in[17];
    float* outp = (float*)d_out;

    void *xga_p, *io_p, *a1_p, *sent_p, *xge_p, *ioe_p, *a2_p, *wt_p;
    cudaGetSymbolAddress(&xga_p, g_xg_intra);
    cudaGetSymbolAddress(&io_p, g_intra_out);
    cudaGetSymbolAddress(&a1_p, g_a1p);
    cudaGetSymbolAddress(&sent_p, g_sent);
    cudaGetSymbolAddress(&xge_p, g_xg_inter);
    cudaGetSymbolAddress(&ioe_p, g_inter_out);
    cudaGetSymbolAddress(&a2_p, g_a2p);
    cudaGetSymbolAddress(&wt_p, g_wt);

    const int sm_k2    = (64 * 132 + 256 * 68) * 4;   // 103424
    const int sm_k256  = (64 * 260 + 128 * 68) * 4;   // 101376
    const int sm_intra = (384 * 132 + 32 * 132) * 4;  // 219648
    const int sm_inter = (384 * 133 + 2 * 132) * 4;
    cudaFuncSetAttribute((const void*)k_gemm2<128, 256, false, false>,
                         cudaFuncAttributeMaxDynamicSharedMemorySize, sm_k2);
    cudaFuncSetAttribute((const void*)k_gemm2<256, 128, false, false>,
                         cudaFuncAttributeMaxDynamicSharedMemorySize, sm_k256);
    cudaFuncSetAttribute((const void*)k_gemm2<256, 128, true, true>,
                         cudaFuncAttributeMaxDynamicSharedMemorySize, sm_k256);
    cudaFuncSetAttribute(k_gru_intra_t, cudaFuncAttributeMaxDynamicSharedMemorySize, sm_intra);
    cudaFuncSetAttribute(k_gru_inter, cudaFuncAttributeMaxDynamicSharedMemorySize, sm_inter);

    // 0) transpose+convert attention weights to tf32
    k_prep_wt<<<dim3(256, 2), 256>>>(WW_a, WW_e, (uint32_t*)wt_p);
    // 1) intra input gates: gathered-embedding GEMM, rows = 131072
    k_gemm2<128, 256, false, false><<<dim3(2048, 3), 256, sm_k2>>>(
        tokens, embed, Wih_a, bih_a, nullptr, (float*)xga_p, 131072);
    // 2) intra biGRU (tensor-core recurrence)
    k_gru_intra_t<<<128, 256, sm_intra>>>((float*)xga_p, Whh_a, bhh_a, (float*)io_p);
    // 3) word attention partial logits (2 column-halves -> 2 planes)
    k_gemm2<256, 128, true, true><<<dim3(2048, 2), 256, sm_k256>>>(
        nullptr, (float*)io_p, (uint32_t*)wt_p, b_a, proj_a, (float*)a1_p, 131072);
    // 4) softmax over tokens (sums planes)
    k_softmax_t<<<8, 256>>>((float*)a1_p);
    // 5) sentence vectors
    k_sent<<<dim3(32, 8), 256>>>((float*)a1_p, (float*)io_p, (float*)sent_p);
    // 6) inter input gates: rows = 2048
    k_gemm2<256, 128, false, false><<<dim3(32, 6), 256, sm_k256>>>(
        nullptr, (float*)sent_p, Wih_e, bih_e, nullptr, (float*)xge_p, 2048);
    // 7) inter biGRU
    k_gru_inter<<<64, 256, sm_inter>>>((float*)xge_p, Whh_e, bhh_e, (float*)ioe_p);
    // 8) sentence attention partial logits (NO softmax)
    k_gemm2<256, 128, true, true><<<dim3(32, 2), 256, sm_k256>>>(
        nullptr, (float*)ioe_p, (uint32_t*)wt_p + 65536, b_e, proj_e, (float*)a2_p, 2048);
    // 9) doc vector + final linear
    k_doc_final<<<64, 256>>>((float*)a2_p, (float*)ioe_p, Wf, bf, outp);
}

// round 8
// speedup vs baseline: 3.0152x; 1.0276x over previous
#include <cuda_runtime.h>
#include <math.h>
#include <stdint.h>

#define S_  32
#define T_  64
#define B_  64
#define C_  5
#define VOCAB_ 32000

// ---------------- scratch (device globals; no allocation) ----------------
__device__ float g_xg_intra[(size_t)2*S_*T_*B_*384]; // [dir][row(s,t,b)][384]
__device__ float g_intra_out[(size_t)S_*T_*B_*256];  // [s][t][b][256] fwd|bwd
__device__ float g_a1p[2*S_*T_*B_];                  // 2 partial planes
__device__ float g_sent[S_*B_*256];
__device__ float g_xg_inter[2*S_*B_*384];            // [dir][row(s,b)][384]
__device__ float g_inter_out[S_*B_*256];
__device__ float g_a2p[2*S_*B_];
__device__ uint32_t g_wt[2*256*256];                 // WW_a, WW_e transposed tf32
__device__ uint32_t g_wih[768*128 + 768*256];        // Wih_a, Wih_e tf32
__device__ uint32_t g_embt[(size_t)VOCAB_*128];      // embed table tf32

__device__ __forceinline__ float sigm(float x) { return 1.f / (1.f + expf(-x)); }

__device__ __forceinline__ uint32_t f2tf(float f) {
    uint32_t o;
    asm("cvt.rna.tf32.f32 %0, %1;" : "=r"(o) : "f"(f));
    return o;
}

__device__ __forceinline__ void mma_tf32(float c[4],
                                         uint32_t a0, uint32_t a1, uint32_t a2, uint32_t a3,
                                         uint32_t b0, uint32_t b1) {
    asm volatile(
        "mma.sync.aligned.m16n8k8.row.col.f32.tf32.tf32.f32 "
        "{%0,%1,%2,%3}, {%4,%5,%6,%7}, {%8,%9}, {%0,%1,%2,%3};"
        : "+f"(c[0]), "+f"(c[1]), "+f"(c[2]), "+f"(c[3])
        : "r"(a0), "r"(a1), "r"(a2), "r"(a3), "r"(b0), "r"(b1));
}

// ---- prep kernels: one-time tf32 conversions ------------------------------
__global__ void k_prep_wt(const float* __restrict__ Wa,
                          const float* __restrict__ We,
                          uint32_t* __restrict__ wt) {
    int idx = blockIdx.x * 256 + threadIdx.x;       // 0..65535
    const float* W = blockIdx.y ? We : Wa;
    int n = idx >> 8, h = idx & 255;
    wt[blockIdx.y * 65536 + n * 256 + h] = f2tf(W[h * 256 + n]);
}

__global__ void k_prep_wih(const float* __restrict__ Wa,
                           const float* __restrict__ We,
                           uint32_t* __restrict__ wih) {
    int idx = blockIdx.x * 256 + threadIdx.x;       // 0..294911
    if (idx < 768 * 128) wih[idx] = f2tf(Wa[idx]);
    else                 wih[idx] = f2tf(We[idx - 768 * 128]);
}

__global__ void k_prep_emb(const float* __restrict__ emb, uint32_t* __restrict__ et) {
    size_t q = (size_t)blockIdx.x * 256 + threadIdx.x;  // 0..1023999 (float4 units)
    float4 v = *(const float4*)(emb + q * 4);
    uint4 u = make_uint4(f2tf(v.x), f2tf(v.y), f2tf(v.z), f2tf(v.w));
    *(uint4*)(et + q * 4) = u;
}

// ============ unified tensor GEMM: 64x128 tiles, 3 blocks/SM ==============
// C[row, col] = sum_k A[row,k] * W[col,k]
// ATTN=false: out[(dir*nrows+row)*384 + (col-384*dir)] = C + bias[col]
// ATTN=true : out[cb*nrows + row] = sum_col proj[col]*tanh(C + bias[col])
// APRE: A already tf32 (uint32); tokens!=null gathers rows via token ids.
template<int KDIM, bool ATTN, bool APRE>
__global__ __launch_bounds__(256, 3) void k_gemm3(const int* __restrict__ tokens,
                                                  const void* __restrict__ Av,
                                                  const uint32_t* __restrict__ Wt,
                                                  const float* __restrict__ bias,
                                                  const float* __restrict__ proj,
                                                  float* __restrict__ out,
                                                  int nrows) {
    extern __shared__ uint32_t usm[];
    uint32_t* As = usm;              // 64 x 68 (64-k chunk)
    uint32_t* Bs = usm + 64 * 68;    // 128 x 68
    __shared__ int toks[64];
    __shared__ float part_sm[4][65];
    const int rb = blockIdx.x, cb = blockIdx.y;
    const int tid = threadIdx.x;
    const int lane = tid & 31, wid = tid >> 5;
    const int wm = wid >> 2, wn = wid & 3;   // 2 (M) x 4 (N)
    const int grp = lane >> 2, t4 = lane & 3;

    if (tokens) {
        if (tid < 64) toks[tid] = tokens[rb * 64 + tid];
        __syncthreads();
    }

    float acc[2][4][4];
#pragma unroll
    for (int i = 0; i < 2; i++)
#pragma unroll
        for (int j = 0; j < 4; j++)
#pragma unroll
            for (int r = 0; r < 4; r++) acc[i][j][r] = 0.f;

#pragma unroll
    for (int kc = 0; kc < KDIM / 64; kc++) {
        if (kc) __syncthreads();
        // A chunk: 64 rows x 64 k
        for (int q = tid; q < 64 * 16; q += 256) {
            int r = q >> 4, w4 = q & 15;
            size_t rowbase = tokens ? (size_t)toks[r] * KDIM
                                    : (size_t)(rb * 64 + r) * KDIM;
            if (APRE) {
                uint4 u = *(const uint4*)((const uint32_t*)Av + rowbase + kc * 64 + w4 * 4);
                *(uint4*)(As + r * 68 + w4 * 4) = u;
            } else {
                float4 v = *(const float4*)((const float*)Av + rowbase + kc * 64 + w4 * 4);
                uint4 u = make_uint4(f2tf(v.x), f2tf(v.y), f2tf(v.z), f2tf(v.w));
                *(uint4*)(As + r * 68 + w4 * 4) = u;
            }
        }
        // B chunk: 128 cols x 64 k (preconverted tf32, [col][k])
        for (int q = tid; q < 128 * 16; q += 256) {
            int n = q >> 4, w4 = q & 15;
            uint4 u = *(const uint4*)(Wt + (size_t)(cb * 128 + n) * KDIM + kc * 64 + w4 * 4);
            *(uint4*)(Bs + n * 68 + w4 * 4) = u;
        }
        __syncthreads();
#pragma unroll
        for (int ks = 0; ks < 8; ks++) {
            const int kb = ks * 8;
            uint32_t a[2][4], b[4][2];
#pragma unroll
            for (int i = 0; i < 2; i++) {
                int row = wm * 32 + i * 16 + grp;
                a[i][0] = As[row * 68 + kb + t4];
                a[i][1] = As[(row + 8) * 68 + kb + t4];
                a[i][2] = As[row * 68 + kb + t4 + 4];
                a[i][3] = As[(row + 8) * 68 + kb + t4 + 4];
            }
#pragma unroll
            for (int j = 0; j < 4; j++) {
                int n = wn * 32 + j * 8 + grp;
                b[j][0] = Bs[n * 68 + kb + t4];
                b[j][1] = Bs[n * 68 + kb + t4 + 4];
            }
#pragma unroll
            for (int i = 0; i < 2; i++)
#pragma unroll
                for (int j = 0; j < 4; j++)
                    mma_tf32(acc[i][j], a[i][0], a[i][1], a[i][2], a[i][3], b[j][0], b[j][1]);
        }
    }

    if (!ATTN) {
#pragma unroll
        for (int i = 0; i < 2; i++) {
            int row = rb * 64 + wm * 32 + i * 16 + grp;
#pragma unroll
            for (int j = 0; j < 4; j++) {
                int col = cb * 128 + wn * 32 + j * 8 + 2 * t4;
                int dir = (col >= 384) ? 1 : 0;
                int g = col - dir * 384;
                float b0v = bias[col], b1v = bias[col + 1];
                float2 v0 = make_float2(acc[i][j][0] + b0v, acc[i][j][1] + b1v);
                float2 v1 = make_float2(acc[i][j][2] + b0v, acc[i][j][3] + b1v);
                *(float2*)&out[((size_t)dir * nrows + row) * 384 + g] = v0;
                *(float2*)&out[((size_t)dir * nrows + row + 8) * 384 + g] = v1;
            }
        }
    } else {
        float rsum[2][2];
#pragma unroll
        for (int i = 0; i < 2; i++) { rsum[i][0] = 0.f; rsum[i][1] = 0.f; }
#pragma unroll
        for (int j = 0; j < 4; j++) {
            int col = cb * 128 + wn * 32 + j * 8 + 2 * t4;
            float pv0 = proj[col], pv1 = proj[col + 1];
            float bv0 = bias[col], bv1 = bias[col + 1];
#pragma unroll
            for (int i = 0; i < 2; i++) {
                rsum[i][0] += pv0 * tanhf(acc[i][j][0] + bv0) + pv1 * tanhf(acc[i][j][1] + bv1);
                rsum[i][1] += pv0 * tanhf(acc[i][j][2] + bv0) + pv1 * tanhf(acc[i][j][3] + bv1);
            }
        }
#pragma unroll
        for (int i = 0; i < 2; i++)
#pragma unroll
            for (int sr = 0; sr < 2; sr++) {
                float v = rsum[i][sr];
                v += __shfl_xor_sync(0xffffffffu, v, 1);
                v += __shfl_xor_sync(0xffffffffu, v, 2);
                if (t4 == 0) part_sm[wn][wm * 32 + i * 16 + sr * 8 + grp] = v;
            }
        __syncthreads();
        if (tid < 64)
            out[(size_t)cb * nrows + rb * 64 + tid] =
                part_sm[0][tid] + part_sm[1][tid] + part_sm[2][tid] + part_sm[3][tid];
    }
}

// ========== K3a: intra biGRU, tensor-core recurrence, 64 steps ============
__global__ __launch_bounds__(256) void k_gru_intra_t(const float* __restrict__ xg,
                                                     const float* __restrict__ Whh,
                                                     const float* __restrict__ bhh,
                                                     float* __restrict__ out) {
    extern __shared__ uint32_t usm[];
    uint32_t* Ws = usm;                        // 384 x 132 tf32 [n][k]
    float* hsm = (float*)(usm + 384 * 132);    // 32 x 132 fp32
    const int bx = blockIdx.x;
    const int dir = bx >> 6, s = (bx >> 1) & 31, bh = bx & 1;
    const int b0 = bh * 32;
    const int tid = threadIdx.x;
    const int lane = tid & 31, w = tid >> 5;
    const int grp = lane >> 2, t4 = lane & 3;

    for (int idx = tid; idx < 384 * 128; idx += 256) {
        int n = idx >> 7, k = idx & 127;
        Ws[n * 132 + k] = f2tf(Whh[dir * 384 * 128 + idx]);
    }
    for (int idx = tid; idx < 32 * 132; idx += 256) hsm[idx] = 0.f;
    __syncthreads();

    const int j2 = 16 * w + 2 * t4;
    float br[2][2], bz[2][2], bn[2][2];
#pragma unroll
    for (int jj = 0; jj < 2; jj++)
#pragma unroll
        for (int c = 0; c < 2; c++) {
            int j = j2 + 8 * jj + c;
            br[jj][c] = bhh[dir * 384 + j];
            bz[jj][c] = bhh[dir * 384 + 128 + j];
            bn[jj][c] = bhh[dir * 384 + 256 + j];
        }

    for (int tt = 0; tt < 64; tt++) {
        const int t = dir ? (63 - tt) : tt;
        const float* xgbase = xg + ((size_t)dir * 131072 + ((s * 64 + t) * 64 + b0)) * 384;

        float2 xr[4][2][3];
#pragma unroll
        for (int ri = 0; ri < 4; ri++) {
            const float* p = xgbase + (size_t)(grp + 8 * ri) * 384 + j2;
#pragma unroll
            for (int jj = 0; jj < 2; jj++) {
                xr[ri][jj][0] = *(const float2*)(p + 8 * jj);
                xr[ri][jj][1] = *(const float2*)(p + 128 + 8 * jj);
                xr[ri][jj][2] = *(const float2*)(p + 256 + 8 * jj);
            }
        }

        float acc[2][6][4];
#pragma unroll
        for (int i = 0; i < 2; i++)
#pragma unroll
            for (int nt = 0; nt < 6; nt++)
#pragma unroll
                for (int r = 0; r < 4; r++) acc[i][nt][r] = 0.f;

#pragma unroll
        for (int ks = 0; ks < 16; ks++) {
            const int k0 = 8 * ks + t4;
            uint32_t ah[2][4], al[2][4];
#pragma unroll
            for (int i = 0; i < 2; i++) {
                float h0 = hsm[(16 * i + grp) * 132 + k0];
                float h1 = hsm[(16 * i + grp + 8) * 132 + k0];
                float h2 = hsm[(16 * i + grp) * 132 + k0 + 4];
                float h3 = hsm[(16 * i + grp + 8) * 132 + k0 + 4];
                ah[i][0] = f2tf(h0); al[i][0] = f2tf(h0 - __uint_as_float(ah[i][0]));
                ah[i][1] = f2tf(h1); al[i][1] = f2tf(h1 - __uint_as_float(ah[i][1]));
                ah[i][2] = f2tf(h2); al[i][2] = f2tf(h2 - __uint_as_float(ah[i][2]));
                ah[i][3] = f2tf(h3); al[i][3] = f2tf(h3 - __uint_as_float(ah[i][3]));
            }
#pragma unroll
            for (int nt = 0; nt < 6; nt++) {
                int n = 128 * (nt >> 1) + 16 * w + 8 * (nt & 1) + grp;
                uint32_t brg0 = Ws[n * 132 + 8 * ks + t4];
                uint32_t brg1 = Ws[n * 132 + 8 * ks + t4 + 4];
                mma_tf32(acc[0][nt], ah[0][0], ah[0][1], ah[0][2], ah[0][3], brg0, brg1);
                mma_tf32(acc[0][nt], al[0][0], al[0][1], al[0][2], al[0][3], brg0, brg1);
                mma_tf32(acc[1][nt], ah[1][0], ah[1][1], ah[1][2], ah[1][3], brg0, brg1);
                mma_tf32(acc[1][nt], al[1][0], al[1][1], al[1][2], al[1][3], brg0, brg1);
            }
        }

        float hn[2][2][2][2];
#pragma unroll
        for (int i = 0; i < 2; i++)
#pragma unroll
            for (int sr = 0; sr < 2; sr++) {
                int ri = 2 * i + sr;
                int row = 16 * i + 8 * sr + grp;
#pragma unroll
                for (int jj = 0; jj < 2; jj++) {
                    float2 ho = *(const float2*)&hsm[row * 132 + j2 + 8 * jj];
                    float r0 = sigm(xr[ri][jj][0].x + acc[i][jj][2 * sr] + br[jj][0]);
                    float r1 = sigm(xr[ri][jj][0].y + acc[i][jj][2 * sr + 1] + br[jj][1]);
                    float z0 = sigm(xr[ri][jj][1].x + acc[i][2 + jj][2 * sr] + bz[jj][0]);
                    float z1 = sigm(xr[ri][jj][1].y + acc[i][2 + jj][2 * sr + 1] + bz[jj][1]);
                    float n0 = tanhf(xr[ri][jj][2].x + r0 * (acc[i][4 + jj][2 * sr] + bn[jj][0]));
                    float n1 = tanhf(xr[ri][jj][2].y + r1 * (acc[i][4 + jj][2 * sr + 1] + bn[jj][1]));
                    float h0 = (1.f - z0) * n0 + z0 * ho.x;
                    float h1 = (1.f - z1) * n1 + z1 * ho.y;
                    hn[i][sr][jj][0] = h0;
                    hn[i][sr][jj][1] = h1;
                    *(float2*)&out[(((size_t)(s * 64 + t)) * 64 + b0 + row) * 256 +
                                   dir * 128 + j2 + 8 * jj] = make_float2(h0, h1);
                }
            }
        __syncthreads();
#pragma unroll
        for (int i = 0; i < 2; i++)
#pragma unroll
            for (int sr = 0; sr < 2; sr++) {
                int row = 16 * i + 8 * sr + grp;
#pragma unroll
                for (int jj = 0; jj < 2; jj++)
                    *(float2*)&hsm[row * 132 + j2 + 8 * jj] =
                        make_float2(hn[i][sr][jj][0], hn[i][sr][jj][1]);
            }
        __syncthreads();
    }
}

// ---------------- K3b: inter biGRU, all 32 steps, one launch --------------
__global__ void k_gru_inter(const float* __restrict__ xg,
                            const float* __restrict__ Whh,
                            const float* __restrict__ bhh,
                            float* __restrict__ out) {
    extern __shared__ float sm[];
    float* Ws = sm;              // 384*133
    float* hs = sm + 384 * 133;  // 2*132
    const int bx = blockIdx.x;
    const int dir = bx >> 5;
    const int b0 = (bx & 31) * 2;
    const int tid = threadIdx.x;
    const int bl = tid >> 7;
    const int j = tid & 127;

    for (int idx = tid; idx < 384 * 128; idx += 256) {
        int row = idx >> 7, k = idx & 127;
        Ws[row * 133 + k] = Whh[dir * 384 * 128 + idx];
    }
    for (int idx = tid; idx < 2 * 132; idx += 256) hs[idx] = 0.f;
    __syncthreads();

    const float br = bhh[dir * 384 + j];
    const float bz = bhh[dir * 384 + 128 + j];
    const float bn = bhh[dir * 384 + 256 + j];

    for (int tt = 0; tt < 32; tt++) {
        const int sstep = dir ? (31 - tt) : tt;
        float ar = 0.f, az = 0.f, an = 0.f;
#pragma unroll 4
        for (int k = 0; k < 128; k++) {
            float hv = hs[bl * 132 + k];
            int ro = j * 133 + k;
            ar = fmaf(hv, Ws[ro], ar);
            az = fmaf(hv, Ws[ro + 128 * 133], az);
            an = fmaf(hv, Ws[ro + 256 * 133], an);
        }
        const int b = b0 + bl;
        const float* xr = xg + (((size_t)dir * 32 + sstep) * 64 + b) * 384;
        float r = sigm(xr[j] + ar + br);
        float z = sigm(xr[128 + j] + az + bz);
        float n = tanhf(xr[256 + j] + r * (an + bn));
        float ho = hs[bl * 132 + j];
        float hv2 = (1.f - z) * n + z * ho;
        out[((size_t)sstep * 64 + b) * 256 + dir * 128 + j] = hv2;
        __syncthreads();
        hs[bl * 132 + j] = hv2;
        __syncthreads();
    }
}

// ------- softmax over t (sums 2 partial planes, writes plane 0) -----------
__global__ void k_softmax_t(float* __restrict__ a) {
    const int NP = S_ * T_ * B_;
    int gid = blockIdx.x * blockDim.x + threadIdx.x;
    if (gid >= S_ * B_) return;
    int s = gid >> 6, b = gid & 63;
    size_t base = (size_t)s * 4096 + b;
    float mx = -1e30f;
    for (int t = 0; t < 64; t++) {
        float v = a[base + t * 64] + a[NP + base + t * 64];
        mx = fmaxf(mx, v);
    }
    float sum = 0.f;
    for (int t = 0; t < 64; t++) {
        float v = a[base + t * 64] + a[NP + base + t * 64];
        sum += expf(v - mx);
    }
    float inv = 1.f / sum;
    for (int t = 0; t < 64; t++) {
        float v = a[base + t * 64] + a[NP + base + t * 64];
        a[base + t * 64] = expf(v - mx) * inv;
    }
}

// ---------------- sentence vectors: sum_t a1 * X ---------------------------
__global__ void k_sent(const float* __restrict__ a1,
                       const float* __restrict__ X,
                       float* __restrict__ sent) {
    const int s = blockIdx.x, bg = blockIdx.y;
    const int h = threadIdx.x;
    float acc[8];
#pragma unroll
    for (int ib = 0; ib < 8; ib++) acc[ib] = 0.f;
    for (int t = 0; t < 64; t++) {
#pragma unroll
        for (int ib = 0; ib < 8; ib++) {
            int b = bg * 8 + ib;
            size_t row = (size_t)s * 4096 + (size_t)t * 64 + b;
            acc[ib] = fmaf(a1[row], X[row * 256 + h], acc[ib]);
        }
    }
#pragma unroll
    for (int ib = 0; ib < 8; ib++)
        sent[((size_t)s * 64 + bg * 8 + ib) * 256 + h] = acc[ib];
}

// --------- doc vector + final linear (sums 2 partial a2 planes) -----------
__global__ void k_doc_final(const float* __restrict__ a2,
                            const float* __restrict__ Xo,
                            const float* __restrict__ Wf,
                            const float* __restrict__ bf,
                            float* __restrict__ outp) {
    __shared__ float red[256];
    const int b = blockIdx.x, h = threadIdx.x;
    float dh = 0.f;
    for (int s2 = 0; s2 < 32; s2++) {
        size_t row = (size_t)s2 * 64 + b;
        float av = a2[row] + a2[S_ * B_ + row];
        dh = fmaf(av, Xo[row * 256 + h], dh);
    }
    for (int c = 0; c < C_; c++) {
        red[h] = dh * Wf[c * 256 + h];
        __syncthreads();
        for (int off = 128; off > 0; off >>= 1) {
            if (h < off) red[h] += red[h + off];
            __syncthreads();
        }
        if (h == 0) outp[b * C_ + c] = red[0] + bf[c];
        __syncthreads();
    }
}

// ---------------- launch ---------------------------------------------------
extern "C" void kernel_launch(void* const* d_in, const int* in_sizes, int n_in,
                              void* d_out, int out_size) {
    const int*   tokens = (const int*)d_in[0];
    const float* embed  = (const float*)d_in[1];
    const float* Wih_a  = (const float*)d_in[2];
    const float* Whh_a  = (const float*)d_in[3];
    const float* bih_a  = (const float*)d_in[4];
    const float* bhh_a  = (const float*)d_in[5];
    const float* WW_a   = (const float*)d_in[6];
    const float* b_a    = (const float*)d_in[7];
    const float* proj_a = (const float*)d_in[8];
    const float* Wih_e  = (const float*)d_in[9];
    const float* Whh_e  = (const float*)d_in[10];
    const float* bih_e  = (const float*)d_in[11];
    const float* bhh_e  = (const float*)d_in[12];
    const float* WW_e   = (const float*)d_in[13];
    const float* b_e    = (const float*)d_in[14];
    const float* proj_e = (const float*)d_in[15];
    const float* Wf     = (const float*)d_in[16];
    const float* bf     = (const float*)d_in[17];
    float* outp = (float*)d_out;

    void *xga_p, *io_p, *a1_p, *sent_p, *xge_p, *ioe_p, *a2_p, *wt_p, *wih_p, *emb_p;
    cudaGetSymbolAddress(&xga_p, g_xg_intra);
    cudaGetSymbolAddress(&io_p, g_intra_out);
    cudaGetSymbolAddress(&a1_p, g_a1p);
    cudaGetSymbolAddress(&sent_p, g_sent);
    cudaGetSymbolAddress(&xge_p, g_xg_inter);
    cudaGetSymbolAddress(&ioe_p, g_inter_out);
    cudaGetSymbolAddress(&a2_p, g_a2p);
    cudaGetSymbolAddress(&wt_p, g_wt);
    cudaGetSymbolAddress(&wih_p, g_wih);
    cudaGetSymbolAddress(&emb_p, g_embt);

    const int sm_gemm  = (64 * 68 + 128 * 68) * 4;    // 52224
    const int sm_intra = (384 * 132 + 32 * 132) * 4;  // 219648
    const int sm_inter = (384 * 133 + 2 * 132) * 4;
    cudaFuncSetAttribute((const void*)k_gemm3<128, false, true>,
                         cudaFuncAttributeMaxDynamicSharedMemorySize, sm_gemm);
    cudaFuncSetAttribute((const void*)k_gemm3<256, false, false>,
                         cudaFuncAttributeMaxDynamicSharedMemorySize, sm_gemm);
    cudaFuncSetAttribute((const void*)k_gemm3<256, true, false>,
                         cudaFuncAttributeMaxDynamicSharedMemorySize, sm_gemm);
    cudaFuncSetAttribute(k_gru_intra_t, cudaFuncAttributeMaxDynamicSharedMemorySize, sm_intra);
    cudaFuncSetAttribute(k_gru_inter, cudaFuncAttributeMaxDynamicSharedMemorySize, sm_inter);

    // 0) one-time tf32 conversions (embed table, gate weights, attention weights)
    k_prep_emb<<<4000, 256>>>(embed, (uint32_t*)emb_p);
    k_prep_wih<<<1152, 256>>>(Wih_a, Wih_e, (uint32_t*)wih_p);
    k_prep_wt<<<dim3(256, 2), 256>>>(WW_a, WW_e, (uint32_t*)wt_p);
    // 1) intra input gates: gathered tf32 GEMM, rows = 131072
    k_gemm3<128, false, true><<<dim3(2048, 6), 256, sm_gemm>>>(
        tokens, (uint32_t*)emb_p, (uint32_t*)wih_p, bih_a, nullptr, (float*)xga_p, 131072);
    // 2) intra biGRU (tensor-core recurrence)
    k_gru_intra_t<<<128, 256, sm_intra>>>((float*)xga_p, Whh_a, bhh_a, (float*)io_p);
    // 3) word attention partial logits (2 column-halves -> 2 planes)
    k_gemm3<256, true, false><<<dim3(2048, 2), 256, sm_gemm>>>(
        nullptr, (float*)io_p, (uint32_t*)wt_p, b_a, proj_a, (float*)a1_p, 131072);
    // 4) softmax over tokens (sums planes)
    k_softmax_t<<<8, 256>>>((float*)a1_p);
    // 5) sentence vectors
    k_sent<<<dim3(32, 8), 256>>>((float*)a1_p, (float*)io_p, (float*)sent_p);
    // 6) inter input gates: rows = 2048
    k_gemm3<256, false, false><<<dim3(32, 6), 256, sm_gemm>>>(
        nullptr, (float*)sent_p, (uint32_t*)wih_p + 768 * 128, bih_e, nullptr,
        (float*)xge_p, 2048);
    // 7) inter biGRU
    k_gru_inter<<<64, 256, sm_inter>>>((float*)xge_p, Whh_e, bhh_e, (float*)ioe_p);
    // 8) sentence attention partial logits (NO softmax)
    k_gemm3<256, true, false><<<dim3(32, 2), 256, sm_gemm>>>(
        nullptr, (float*)ioe_p, (uint32_t*)wt_p + 65536, b_e, proj_e, (float*)a2_p, 2048);
    // 9) doc vector + final linear
    k_doc_final<<<64, 256>>>((float*)a2_p, (float*)ioe_p, Wf, bf, outp);
}

// round 10
// speedup vs baseline: 3.7828x; 1.2546x over previous
#include <cuda_runtime.h>
#include <cuda_fp16.h>
#include <math.h>
#include <stdint.h>

#define S_  32
#define T_  64
#define B_  64
#define C_  5
#define VOCAB_ 32000

// ---------------- scratch (device globals; no allocation) ----------------
__device__ float g_xg_intra[(size_t)2*S_*T_*B_*384]; // [dir][row(s,t,b)][384]
__device__ float g_intra_out[(size_t)S_*T_*B_*256];  // [s][t][b][256] fwd|bwd
__device__ float g_a1p[2*S_*T_*B_];                  // 2 partial planes
__device__ float g_sent[S_*B_*256];
__device__ float g_xg_inter[2*S_*B_*384];
__device__ float g_inter_out[S_*B_*256];
__device__ float g_a2p[2*S_*B_];
// fp16 preconversions
__device__ uint16_t g_emb_h[(size_t)VOCAB_*128];     // embed table half
__device__ uint16_t g_wihA_h[768*128];               // Wih_a half [col][k]
__device__ uint16_t g_wihE_h[768*256];               // Wih_e half [col][k]
__device__ uint16_t g_ww_h[2*256*256];               // WW_a/WW_e transposed half [n][k]

__device__ __forceinline__ float sigm(float x) { return 1.f / (1.f + expf(-x)); }

__device__ __forceinline__ uint32_t f2h2(float x, float y) {
    __half2 h = __floats2half2_rn(x, y);
    return *(uint32_t*)&h;
}
// 2-term split: hi = rn(x,y); lo = rn(residual)
__device__ __forceinline__ void split_h2(float x, float y, uint32_t& hi, uint32_t& lo) {
    __half hx = __float2half_rn(x), hy = __float2half_rn(y);
    __half lx = __float2half_rn(x - __half2float(hx));
    __half ly = __float2half_rn(y - __half2float(hy));
    hi = ((uint32_t)(*(uint16_t*)&hy) << 16) | (uint32_t)(*(uint16_t*)&hx);
    lo = ((uint32_t)(*(uint16_t*)&ly) << 16) | (uint32_t)(*(uint16_t*)&lx);
}

__device__ __forceinline__ void mma_f16(float c[4],
                                        uint32_t a0, uint32_t a1, uint32_t a2, uint32_t a3,
                                        uint32_t b0, uint32_t b1) {
    asm volatile(
        "mma.sync.aligned.m16n8k16.row.col.f32.f16.f16.f32 "
        "{%0,%1,%2,%3}, {%4,%5,%6,%7}, {%8,%9}, {%0,%1,%2,%3};"
        : "+f"(c[0]), "+f"(c[1]), "+f"(c[2]), "+f"(c[3])
        : "r"(a0), "r"(a1), "r"(a2), "r"(a3), "r"(b0), "r"(b1));
}

// ---- prep kernels: one-time fp16 conversions ------------------------------
// generic: 8 floats per thread -> 8 halves (4 packed words)
__global__ void k_prep_h(const float* __restrict__ in, uint16_t* __restrict__ out) {
    size_t q = ((size_t)blockIdx.x * 256 + threadIdx.x) * 8;
    float4 v0 = *(const float4*)(in + q);
    float4 v1 = *(const float4*)(in + q + 4);
    uint4 u = make_uint4(f2h2(v0.x, v0.y), f2h2(v0.z, v0.w),
                         f2h2(v1.x, v1.y), f2h2(v1.z, v1.w));
    *(uint4*)(out + q) = u;
}
// attention weights: transpose [h][n] -> [n][k=h], convert
__global__ void k_prep_ww_h(const float* __restrict__ Wa, const float* __restrict__ We,
                            uint16_t* __restrict__ out) {
    int idx = blockIdx.x * 256 + threadIdx.x;       // 0..65535
    const float* W = blockIdx.y ? We : Wa;
    int n = idx >> 8, h = idx & 255;
    __half v = __float2half_rn(W[h * 256 + n]);
    out[blockIdx.y * 65536 + n * 256 + h] = *(uint16_t*)&v;
}

// ============ unified fp16 tensor GEMM: 64x128 tiles, 3 blocks/SM =========
// C[row, col] = sum_k A[row,k] * W[col,k]   (W preconverted half [col][k])
// ATTN=false: out[(dir*nrows+row)*384 + (col-384*dir)] = C + bias[col]
// ATTN=true : out[cb*nrows + row] = sum_col proj[col]*tanh(C + bias[col])
// AHALF: A preconverted half (uint16); tokens!=null gathers rows.
template<int KDIM, bool ATTN, bool AHALF>
__global__ __launch_bounds__(256, 3) void k_gemm4(const int* __restrict__ tokens,
                                                  const void* __restrict__ Av,
                                                  const uint16_t* __restrict__ Wt,
                                                  const float* __restrict__ bias,
                                                  const float* __restrict__ proj,
                                                  float* __restrict__ out,
                                                  int nrows) {
    extern __shared__ uint32_t usm[];
    uint32_t* As = usm;              // 64 rows x 36 words (64-k chunk as half2)
    uint32_t* Bs = usm + 64 * 36;    // 128 cols x 36 words
    __shared__ int toks[64];
    __shared__ float part_sm[4][65];
    const int rb = blockIdx.x, cb = blockIdx.y;
    const int tid = threadIdx.x;
    const int lane = tid & 31, wid = tid >> 5;
    const int wm = wid >> 2, wn = wid & 3;   // 2 (M) x 4 (N)
    const int grp = lane >> 2, t4 = lane & 3;

    if (tokens) {
        if (tid < 64) toks[tid] = tokens[rb * 64 + tid];
        __syncthreads();
    }

    float acc[2][4][4];
#pragma unroll
    for (int i = 0; i < 2; i++)
#pragma unroll
        for (int j = 0; j < 4; j++)
#pragma unroll
            for (int r = 0; r < 4; r++) acc[i][j][r] = 0.f;

#pragma unroll
    for (int kc = 0; kc < KDIM / 64; kc++) {
        if (kc) __syncthreads();
        // A chunk: 64 rows x 64 k (8 halves per uint4)
        for (int q = tid; q < 64 * 8; q += 256) {
            int r = q >> 3, u = q & 7;
            size_t rowbase = tokens ? (size_t)toks[r] * KDIM
                                    : (size_t)(rb * 64 + r) * KDIM;
            if (AHALF) {
                uint4 v = *(const uint4*)((const uint16_t*)Av + rowbase + kc * 64 + u * 8);
                *(uint4*)(As + r * 36 + u * 4) = v;
            } else {
                const float* src = (const float*)Av + rowbase + kc * 64 + u * 8;
                float4 v0 = *(const float4*)src;
                float4 v1 = *(const float4*)(src + 4);
                *(uint4*)(As + r * 36 + u * 4) =
                    make_uint4(f2h2(v0.x, v0.y), f2h2(v0.z, v0.w),
                               f2h2(v1.x, v1.y), f2h2(v1.z, v1.w));
            }
        }
        // B chunk: 128 cols x 64 k (preconverted half)
        for (int q = tid; q < 128 * 8; q += 256) {
            int n = q >> 3, u = q & 7;
            uint4 v = *(const uint4*)(Wt + (size_t)(cb * 128 + n) * KDIM + kc * 64 + u * 8);
            *(uint4*)(Bs + n * 36 + u * 4) = v;
        }
        __syncthreads();
#pragma unroll
        for (int ks = 0; ks < 4; ks++) {          // 4 x k16 per 64-k chunk
            const int kb = ks * 8;
            uint32_t a[2][4], b[4][2];
#pragma unroll
            for (int i = 0; i < 2; i++) {
                int row = wm * 32 + i * 16 + grp;
                a[i][0] = As[row * 36 + kb + t4];
                a[i][1] = As[(row + 8) * 36 + kb + t4];
                a[i][2] = As[row * 36 + kb + 4 + t4];
                a[i][3] = As[(row + 8) * 36 + kb + 4 + t4];
            }
#pragma unroll
            for (int j = 0; j < 4; j++) {
                int n = wn * 32 + j * 8 + grp;
                b[j][0] = Bs[n * 36 + kb + t4];
                b[j][1] = Bs[n * 36 + kb + 4 + t4];
            }
#pragma unroll
            for (int i = 0; i < 2; i++)
#pragma unroll
                for (int j = 0; j < 4; j++)
                    mma_f16(acc[i][j], a[i][0], a[i][1], a[i][2], a[i][3], b[j][0], b[j][1]);
        }
    }

    if (!ATTN) {
#pragma unroll
        for (int i = 0; i < 2; i++) {
            int row = rb * 64 + wm * 32 + i * 16 + grp;
#pragma unroll
            for (int j = 0; j < 4; j++) {
                int col = cb * 128 + wn * 32 + j * 8 + 2 * t4;
                int dir = (col >= 384) ? 1 : 0;
                int g = col - dir * 384;
                float b0v = bias[col], b1v = bias[col + 1];
                float2 v0 = make_float2(acc[i][j][0] + b0v, acc[i][j][1] + b1v);
                float2 v1 = make_float2(acc[i][j][2] + b0v, acc[i][j][3] + b1v);
                *(float2*)&out[((size_t)dir * nrows + row) * 384 + g] = v0;
                *(float2*)&out[((size_t)dir * nrows + row + 8) * 384 + g] = v1;
            }
        }
    } else {
        float rsum[2][2];
#pragma unroll
        for (int i = 0; i < 2; i++) { rsum[i][0] = 0.f; rsum[i][1] = 0.f; }
#pragma unroll
        for (int j = 0; j < 4; j++) {
            int col = cb * 128 + wn * 32 + j * 8 + 2 * t4;
            float pv0 = proj[col], pv1 = proj[col + 1];
            float bv0 = bias[col], bv1 = bias[col + 1];
#pragma unroll
            for (int i = 0; i < 2; i++) {
                rsum[i][0] += pv0 * tanhf(acc[i][j][0] + bv0) + pv1 * tanhf(acc[i][j][1] + bv1);
                rsum[i][1] += pv0 * tanhf(acc[i][j][2] + bv0) + pv1 * tanhf(acc[i][j][3] + bv1);
            }
        }
#pragma unroll
        for (int i = 0; i < 2; i++)
#pragma unroll
            for (int sr = 0; sr < 2; sr++) {
                float v = rsum[i][sr];
                v += __shfl_xor_sync(0xffffffffu, v, 1);
                v += __shfl_xor_sync(0xffffffffu, v, 2);
                if (t4 == 0) part_sm[wn][wm * 32 + i * 16 + sr * 8 + grp] = v;
            }
        __syncthreads();
        if (tid < 64)
            out[(size_t)cb * nrows + rb * 64 + tid] =
                part_sm[0][tid] + part_sm[1][tid] + part_sm[2][tid] + part_sm[3][tid];
    }
}

// ========== K3a: intra biGRU, fp16 tensor recurrence, 64 steps ============
// grid 128: dir = bx>>6, s = (bx>>1)&31, bhalf = bx&1 (32 batch rows/block)
// warp w owns hidden slice [16w,16w+16) for all 3 gates (thread-local gates).
// h split hi+lo fp16 (2-term); Whh single fp16 in smem (stride 68 words).
__global__ __launch_bounds__(256) void k_gru_intra_t(const float* __restrict__ xg,
                                                     const float* __restrict__ Whh,
                                                     const float* __restrict__ bhh,
                                                     float* __restrict__ out) {
    extern __shared__ uint32_t usm[];
    uint32_t* Ws = usm;                       // 384 x 68 words (half2 [n][kw])
    float* hsm = (float*)(usm + 384 * 68);    // 32 x 132 fp32
    const int bx = blockIdx.x;
    const int dir = bx >> 6, s = (bx >> 1) & 31, bh = bx & 1;
    const int b0 = bh * 32;
    const int tid = threadIdx.x;
    const int lane = tid & 31, w = tid >> 5;
    const int grp = lane >> 2, t4 = lane & 3;

    for (int idx = tid; idx < 384 * 64; idx += 256) {
        int n = idx >> 6, kw = idx & 63;
        const float* p = Whh + dir * 384 * 128 + n * 128 + kw * 2;
        Ws[n * 68 + kw] = f2h2(p[0], p[1]);
    }
    for (int idx = tid; idx < 32 * 132; idx += 256) hsm[idx] = 0.f;
    __syncthreads();

    const int j2 = 16 * w + 2 * t4;
    float br[2][2], bz[2][2], bn[2][2];
#pragma unroll
    for (int jj = 0; jj < 2; jj++)
#pragma unroll
        for (int c = 0; c < 2; c++) {
            int j = j2 + 8 * jj + c;
            br[jj][c] = bhh[dir * 384 + j];
            bz[jj][c] = bhh[dir * 384 + 128 + j];
            bn[jj][c] = bhh[dir * 384 + 256 + j];
        }

    for (int tt = 0; tt < 64; tt++) {
        const int t = dir ? (63 - tt) : tt;
        const float* xgbase = xg + ((size_t)dir * 131072 + ((s * 64 + t) * 64 + b0)) * 384;

        float2 xr[4][2][3];
#pragma unroll
        for (int ri = 0; ri < 4; ri++) {
            const float* p = xgbase + (size_t)(grp + 8 * ri) * 384 + j2;
#pragma unroll
            for (int jj = 0; jj < 2; jj++) {
                xr[ri][jj][0] = *(const float2*)(p + 8 * jj);
                xr[ri][jj][1] = *(const float2*)(p + 128 + 8 * jj);
                xr[ri][jj][2] = *(const float2*)(p + 256 + 8 * jj);
            }
        }

        float acc[2][6][4];
#pragma unroll
        for (int i = 0; i < 2; i++)
#pragma unroll
            for (int nt = 0; nt < 6; nt++)
#pragma unroll
                for (int r = 0; r < 4; r++) acc[i][nt][r] = 0.f;

#pragma unroll
        for (int ks = 0; ks < 8; ks++) {          // 8 x k16 over K=128
            uint32_t ah[2][4], al[2][4];
#pragma unroll
            for (int i = 0; i < 2; i++) {
                float2 p0 = *(const float2*)&hsm[(16 * i + grp) * 132 + 16 * ks + 2 * t4];
                float2 p1 = *(const float2*)&hsm[(16 * i + 8 + grp) * 132 + 16 * ks + 2 * t4];
                float2 p2 = *(const float2*)&hsm[(16 * i + grp) * 132 + 16 * ks + 8 + 2 * t4];
                float2 p3 = *(const float2*)&hsm[(16 * i + 8 + grp) * 132 + 16 * ks + 8 + 2 * t4];
                split_h2(p0.x, p0.y, ah[i][0], al[i][0]);
                split_h2(p1.x, p1.y, ah[i][1], al[i][1]);
                split_h2(p2.x, p2.y, ah[i][2], al[i][2]);
                split_h2(p3.x, p3.y, ah[i][3], al[i][3]);
            }
            const int kb = ks * 8;
#pragma unroll
            for (int nt = 0; nt < 6; nt++) {
                int n = 128 * (nt >> 1) + 16 * w + 8 * (nt & 1) + grp;
                uint32_t brg0 = Ws[n * 68 + kb + t4];
                uint32_t brg1 = Ws[n * 68 + kb + 4 + t4];
                mma_f16(acc[0][nt], ah[0][0], ah[0][1], ah[0][2], ah[0][3], brg0, brg1);
                mma_f16(acc[0][nt], al[0][0], al[0][1], al[0][2], al[0][3], brg0, brg1);
                mma_f16(acc[1][nt], ah[1][0], ah[1][1], ah[1][2], ah[1][3], brg0, brg1);
                mma_f16(acc[1][nt], al[1][0], al[1][1], al[1][2], al[1][3], brg0, brg1);
            }
        }

        float hn[2][2][2][2];
#pragma unroll
        for (int i = 0; i < 2; i++)
#pragma unroll
            for (int sr = 0; sr < 2; sr++) {
                int ri = 2 * i + sr;
                int row = 16 * i + 8 * sr + grp;
#pragma unroll
                for (int jj = 0; jj < 2; jj++) {
                    float2 ho = *(const float2*)&hsm[row * 132 + j2 + 8 * jj];
                    float r0 = sigm(xr[ri][jj][0].x + acc[i][jj][2 * sr] + br[jj][0]);
                    float r1 = sigm(xr[ri][jj][0].y + acc[i][jj][2 * sr + 1] + br[jj][1]);
                    float z0 = sigm(xr[ri][jj][1].x + acc[i][2 + jj][2 * sr] + bz[jj][0]);
                    float z1 = sigm(xr[ri][jj][1].y + acc[i][2 + jj][2 * sr + 1] + bz[jj][1]);
                    float n0 = tanhf(xr[ri][jj][2].x + r0 * (acc[i][4 + jj][2 * sr] + bn[jj][0]));
                    float n1 = tanhf(xr[ri][jj][2].y + r1 * (acc[i][4 + jj][2 * sr + 1] + bn[jj][1]));
                    float h0 = (1.f - z0) * n0 + z0 * ho.x;
                    float h1 = (1.f - z1) * n1 + z1 * ho.y;
                    hn[i][sr][jj][0] = h0;
                    hn[i][sr][jj][1] = h1;
                    *(float2*)&out[(((size_t)(s * 64 + t)) * 64 + b0 + row) * 256 +
                                   dir * 128 + j2 + 8 * jj] = make_float2(h0, h1);
                }
            }
        __syncthreads();
#pragma unroll
        for (int i = 0; i < 2; i++)
#pragma unroll
            for (int sr = 0; sr < 2; sr++) {
                int row = 16 * i + 8 * sr + grp;
#pragma unroll
                for (int jj = 0; jj < 2; jj++)
                    *(float2*)&hsm[row * 132 + j2 + 8 * jj] =
                        make_float2(hn[i][sr][jj][0], hn[i][sr][jj][1]);
            }
        __syncthreads();
    }
}

// ---------------- K3b: inter biGRU (small, SIMT) --------------------------
__global__ void k_gru_inter(const float* __restrict__ xg,
                            const float* __restrict__ Whh,
                            const float* __restrict__ bhh,
                            float* __restrict__ out) {
    extern __shared__ float sm[];
    float* Ws = sm;              // 384*133
    float* hs = sm + 384 * 133;  // 2*132
    const int bx = blockIdx.x;
    const int dir = bx >> 5;
    const int b0 = (bx & 31) * 2;
    const int tid = threadIdx.x;
    const int bl = tid >> 7;
    const int j = tid & 127;

    for (int idx = tid; idx < 384 * 128; idx += 256) {
        int row = idx >> 7, k = idx & 127;
        Ws[row * 133 + k] = Whh[dir * 384 * 128 + idx];
    }
    for (int idx = tid; idx < 2 * 132; idx += 256) hs[idx] = 0.f;
    __syncthreads();

    const float br = bhh[dir * 384 + j];
    const float bz = bhh[dir * 384 + 128 + j];
    const float bn = bhh[dir * 384 + 256 + j];

    for (int tt = 0; tt < 32; tt++) {
        const int sstep = dir ? (31 - tt) : tt;
        float ar = 0.f, az = 0.f, an = 0.f;
#pragma unroll 4
        for (int k = 0; k < 128; k++) {
            float hv = hs[bl * 132 + k];
            int ro = j * 133 + k;
            ar = fmaf(hv, Ws[ro], ar);
            az = fmaf(hv, Ws[ro + 128 * 133], az);
            an = fmaf(hv, Ws[ro + 256 * 133], an);
        }
        const int b = b0 + bl;
        const float* xr = xg + (((size_t)dir * 32 + sstep) * 64 + b) * 384;
        float r = sigm(xr[j] + ar + br);
        float z = sigm(xr[128 + j] + az + bz);
        float n = tanhf(xr[256 + j] + r * (an + bn));
        float ho = hs[bl * 132 + j];
        float hv2 = (1.f - z) * n + z * ho;
        out[((size_t)sstep * 64 + b) * 256 + dir * 128 + j] = hv2;
        __syncthreads();
        hs[bl * 132 + j] = hv2;
        __syncthreads();
    }
}

// ------- softmax over t (sums 2 partial planes, writes plane 0) -----------
__global__ void k_softmax_t(float* __restrict__ a) {
    const int NP = S_ * T_ * B_;
    int gid = blockIdx.x * blockDim.x + threadIdx.x;
    if (gid >= S_ * B_) return;
    int s = gid >> 6, b = gid & 63;
    size_t base = (size_t)s * 4096 + b;
    float mx = -1e30f;
    for (int t = 0; t < 64; t++) {
        float v = a[base + t * 64] + a[NP + base + t * 64];
        mx = fmaxf(mx, v);
    }
    float sum = 0.f;
    for (int t = 0; t < 64; t++) {
        float v = a[base + t * 64] + a[NP + base + t * 64];
        sum += expf(v - mx);
    }
    float inv = 1.f / sum;
    for (int t = 0; t < 64; t++) {
        float v = a[base + t * 64] + a[NP + base + t * 64];
        a[base + t * 64] = expf(v - mx) * inv;
    }
}

// ---------------- sentence vectors: sum_t a1 * X ---------------------------
__global__ void k_sent(const float* __restrict__ a1,
                       const float* __restrict__ X,
                       float* __restrict__ sent) {
    const int s = blockIdx.x, bg = blockIdx.y;
    const int h = threadIdx.x;
    float acc[8];
#pragma unroll
    for (int ib = 0; ib < 8; ib++) acc[ib] = 0.f;
    for (int t = 0; t < 64; t++) {
#pragma unroll
        for (int ib = 0; ib < 8; ib++) {
            int b = bg * 8 + ib;
            size_t row = (size_t)s * 4096 + (size_t)t * 64 + b;
            acc[ib] = fmaf(a1[row], X[row * 256 + h], acc[ib]);
        }
    }
#pragma unroll
    for (int ib = 0; ib < 8; ib++)
        sent[((size_t)s * 64 + bg * 8 + ib) * 256 + h] = acc[ib];
}

// --------- doc vector + final linear (sums 2 partial a2 planes) -----------
__global__ void k_doc_final(const float* __restrict__ a2,
                            const float* __restrict__ Xo,
                            const float* __restrict__ Wf,
                            const float* __restrict__ bf,
                            float* __restrict__ outp) {
    __shared__ float red[256];
    const int b = blockIdx.x, h = threadIdx.x;
    float dh = 0.f;
    for (int s2 = 0; s2 < 32; s2++) {
        size_t row = (size_t)s2 * 64 + b;
        float av = a2[row] + a2[S_ * B_ + row];
        dh = fmaf(av, Xo[row * 256 + h], dh);
    }
    for (int c = 0; c < C_; c++) {
        red[h] = dh * Wf[c * 256 + h];
        __syncthreads();
        for (int off = 128; off > 0; off >>= 1) {
            if (h < off) red[h] += red[h + off];
            __syncthreads();
        }
        if (h == 0) outp[b * C_ + c] = red[0] + bf[c];
        __syncthreads();
    }
}

// ---------------- launch ---------------------------------------------------
extern "C" void kernel_launch(void* const* d_in, const int* in_sizes, int n_in,
                              void* d_out, int out_size) {
    const int*   tokens = (const int*)d_in[0];
    const float* embed  = (const float*)d_in[1];
    const float* Wih_a  = (const float*)d_in[2];
    const float* Whh_a  = (const float*)d_in[3];
    const float* bih_a  = (const float*)d_in[4];
    const float* bhh_a  = (const float*)d_in[5];
    const float* WW_a   = (const float*)d_in[6];
    const float* b_a    = (const float*)d_in[7];
    const float* proj_a = (const float*)d_in[8];
    const float* Wih_e  = (const float*)d_in[9];
    const float* Whh_e  = (const float*)d_in[10];
    const float* bih_e  = (const float*)d_in[11];
    const float* bhh_e  = (const float*)d_in[12];
    const float* WW_e   = (const float*)d_in[13];
    const float* b_e    = (const float*)d_in[14];
    const float* proj_e = (const float*)d_in[15];
    const float* Wf     = (const float*)d_in[16];
    const float* bf     = (const float*)d_in[17];
    float* outp = (float*)d_out;

    void *xga_p, *io_p, *a1_p, *sent_p, *xge_p, *ioe_p, *a2_p;
    void *embh_p, *wihA_p, *wihE_p, *ww_p;
    cudaGetSymbolAddress(&xga_p, g_xg_intra);
    cudaGetSymbolAddress(&io_p, g_intra_out);
    cudaGetSymbolAddress(&a1_p, g_a1p);
    cudaGetSymbolAddress(&sent_p, g_sent);
    cudaGetSymbolAddress(&xge_p, g_xg_inter);
    cudaGetSymbolAddress(&ioe_p, g_inter_out);
    cudaGetSymbolAddress(&a2_p, g_a2p);
    cudaGetSymbolAddress(&embh_p, g_emb_h);
    cudaGetSymbolAddress(&wihA_p, g_wihA_h);
    cudaGetSymbolAddress(&wihE_p, g_wihE_h);
    cudaGetSymbolAddress(&ww_p, g_ww_h);

    const int sm_gemm  = (64 * 36 + 128 * 36) * 4;    // 27648
    const int sm_intra = (384 * 68 + 32 * 132) * 4;   // 121344
    const int sm_inter = (384 * 133 + 2 * 132) * 4;
    cudaFuncSetAttribute((const void*)k_gemm4<128, false, true>,
                         cudaFuncAttributeMaxDynamicSharedMemorySize, sm_gemm);
    cudaFuncSetAttribute((const void*)k_gemm4<256, false, false>,
                         cudaFuncAttributeMaxDynamicSharedMemorySize, sm_gemm);
    cudaFuncSetAttribute((const void*)k_gemm4<256, true, false>,
                         cudaFuncAttributeMaxDynamicSharedMemorySize, sm_gemm);
    cudaFuncSetAttribute(k_gru_intra_t, cudaFuncAttributeMaxDynamicSharedMemorySize, sm_intra);
    cudaFuncSetAttribute(k_gru_inter, cudaFuncAttributeMaxDynamicSharedMemorySize, sm_inter);

    // 0) one-time fp16 conversions
    k_prep_h<<<2000, 256>>>(embed, (uint16_t*)embh_p);            // 32000*128
    k_prep_h<<<48, 256>>>(Wih_a, (uint16_t*)wihA_p);              // 768*128
    k_prep_h<<<96, 256>>>(Wih_e, (uint16_t*)wihE_p);              // 768*256
    k_prep_ww_h<<<dim3(256, 2), 256>>>(WW_a, WW_e, (uint16_t*)ww_p);
    // 1) intra input gates: gathered fp16 GEMM, rows = 131072
    k_gemm4<128, false, true><<<dim3(2048, 6), 256, sm_gemm>>>(
        tokens, (uint16_t*)embh_p, (uint16_t*)wihA_p, bih_a, nullptr,
        (float*)xga_p, 131072);
    // 2) intra biGRU (fp16 tensor recurrence)
    k_gru_intra_t<<<128, 256, sm_intra>>>((float*)xga_p, Whh_a, bhh_a, (float*)io_p);
    // 3) word attention partial logits (2 column-halves -> 2 planes)
    k_gemm4<256, true, false><<<dim3(2048, 2), 256, sm_gemm>>>(
        nullptr, (float*)io_p, (uint16_t*)ww_p, b_a, proj_a, (float*)a1_p, 131072);
    // 4) softmax over tokens (sums planes)
    k_softmax_t<<<8, 256>>>((float*)a1_p);
    // 5) sentence vectors
    k_sent<<<dim3(32, 8), 256>>>((float*)a1_p, (float*)io_p, (float*)sent_p);
    // 6) inter input gates: rows = 2048
    k_gemm4<256, false, false><<<dim3(32, 6), 256, sm_gemm>>>(
        nullptr, (float*)sent_p, (uint16_t*)wihE_p, bih_e, nullptr,
        (float*)xge_p, 2048);
    // 7) inter biGRU
    k_gru_inter<<<64, 256, sm_inter>>>((float*)xge_p, Whh_e, bhh_e, (float*)ioe_p);
    // 8) sentence attention partial logits (NO softmax)
    k_gemm4<256, true, false><<<dim3(32, 2), 256, sm_gemm>>>(
        nullptr, (float*)ioe_p, (uint16_t*)ww_p + 65536, b_e, proj_e, (float*)a2_p, 2048);
    // 9) doc vector + final linear
    k_doc_final<<<64, 256>>>((float*)a2_p, (float*)ioe_p, Wf, bf, outp);
}